// round 3
// baseline (speedup 1.0000x reference)
#include <cuda_runtime.h>
#include <math.h>

#define N_NODES 16384
#define IN_DIM  256
#define HEADS   2
#define OUT_CH  256
#define F_DIM   512              // HEADS*OUT_CH
#define E_IN    524288
#define E_TOT   (E_IN + N_NODES) // with self loops

// ---------------- scratch (device globals; no allocation allowed) ----------
__device__ float    g_h   [N_NODES * F_DIM];   // x @ conv_W.T
__device__ float    g_gat [N_NODES * F_DIM];   // aggregated GAT output
__device__ float    g_as  [N_NODES * HEADS];
__device__ float    g_ad  [N_NODES * HEADS];
__device__ unsigned g_emax[N_NODES * HEADS];   // ordered-uint encoded max
__device__ float    g_esum[N_NODES * HEADS];
__device__ float    g_w   [E_TOT * HEADS];     // exp(e - max) per edge/head
__device__ float    g_h1  [N_NODES * 256];
__device__ float    g_h2  [N_NODES * 128];
__device__ float    g_h3  [N_NODES * 64];
__device__ float    g_h4  [N_NODES * 32];
__device__ float    g_h5  [N_NODES * 4];       // 3 coords + pad (float4 friendly)
__device__ int      g_is64;                    // edge_index dtype flag

// device-side scratch-buffer resolver: NO host symbol-address APIs needed
#define BUF_H   0
#define BUF_GAT 1
#define BUF_H1  2
#define BUF_H2  3
#define BUF_H3  4
#define BUF_H4  5
__device__ __forceinline__ float* buf_ptr(int id) {
    switch (id) {
        case BUF_H:   return g_h;
        case BUF_GAT: return g_gat;
        case BUF_H1:  return g_h1;
        case BUF_H2:  return g_h2;
        case BUF_H3:  return g_h3;
        default:      return g_h4;
    }
}

// ---------------- helpers ---------------------------------------------------
__device__ __forceinline__ unsigned enc_f(float v) {
    unsigned u = __float_as_uint(v);
    return (u & 0x80000000u) ? ~u : (u | 0x80000000u);
}
__device__ __forceinline__ float dec_f(unsigned u) {
    unsigned b = (u & 0x80000000u) ? (u ^ 0x80000000u) : ~u;
    return __uint_as_float(b);
}
// FFMA-pipe sqrt: magic rsqrt + 2 Newton iters (avoids MUFU throughput wall)
__device__ __forceinline__ float fast_sqrt(float d2) {
    float r = __uint_as_float(0x5f3759dfu - (__float_as_uint(d2) >> 1));
    float hd = 0.5f * d2;
    r = r * fmaf(-(hd * r), r, 1.5f);
    r = r * fmaf(-(hd * r), r, 1.5f);
    return d2 * r;   // d2==0 -> 0 (no inf/NaN: magic rsqrt(0) is finite)
}

// ---------------- edge_index dtype probe (deterministic) --------------------
__global__ void detect_idx_kernel(const void* __restrict__ ei) {
    if (threadIdx.x == 0 && blockIdx.x == 0) {
        const long long* p = (const long long*)ei;
        int ok64 = 1;
        for (int i = 0; i < 256; i++) {
            long long v = p[i];
            if (v < 0 || v >= N_NODES) { ok64 = 0; break; }
        }
        g_is64 = ok64;
    }
}

__device__ __forceinline__ void edge_nodes(const void* __restrict__ ei, int e,
                                           int& src, int& dst) {
    if (e >= E_IN) { src = dst = e - E_IN; return; }
    if (g_is64) {
        const long long* p = (const long long*)ei;
        src = (int)p[e]; dst = (int)p[E_IN + e];
    } else {
        const int* p = (const int*)ei;
        src = p[e]; dst = p[E_IN + e];
    }
    src = min(max(src, 0), N_NODES - 1);
    dst = min(max(dst, 0), N_NODES - 1);
}

// ---------------- zero init (graph replays!) --------------------------------
__global__ void zero_gat_kernel() {
    int i = blockIdx.x * blockDim.x + threadIdx.x;
    if (i < N_NODES * F_DIM / 4)
        ((float4*)g_gat)[i] = make_float4(0.f, 0.f, 0.f, 0.f);
}
__global__ void zero_stats_kernel() {
    int i = blockIdx.x * blockDim.x + threadIdx.x;
    if (i < N_NODES * HEADS) { g_emax[i] = 0u; g_esum[i] = 0.f; }
}

// ---------------- tiled fp32 GEMM: C[M,Nout] = act(A[M,K] @ W[Nout,K]^T + b)
__global__ __launch_bounds__(256)
void gemm_kernel(const float* __restrict__ a_raw, int a_id,
                 const float* __restrict__ W, const float* __restrict__ bias,
                 int c_id, int M, int Nout, int K, int doRelu) {
    const float* A = a_raw ? a_raw : (const float*)buf_ptr(a_id);
    float* C = buf_ptr(c_id);

    __shared__ float As[16][64];
    __shared__ float Ws[16][64];
    const int tid = threadIdx.x;
    const int tx = tid & 15, ty = tid >> 4;
    const int m0 = blockIdx.y * 64;
    const int n0 = blockIdx.x * 64;
    const int lr = tid >> 2;          // 0..63
    const int lc = (tid & 3) * 4;     // 0,4,8,12

    float acc[4][4];
    #pragma unroll
    for (int i = 0; i < 4; i++)
        #pragma unroll
        for (int j = 0; j < 4; j++) acc[i][j] = 0.f;

    for (int kt = 0; kt < K; kt += 16) {
        float4 av = *(const float4*)&A[(size_t)(m0 + lr) * K + kt + lc];
        As[lc + 0][lr] = av.x; As[lc + 1][lr] = av.y;
        As[lc + 2][lr] = av.z; As[lc + 3][lr] = av.w;
        float4 wv = make_float4(0.f, 0.f, 0.f, 0.f);
        if (n0 + lr < Nout)
            wv = *(const float4*)&W[(size_t)(n0 + lr) * K + kt + lc];
        Ws[lc + 0][lr] = wv.x; Ws[lc + 1][lr] = wv.y;
        Ws[lc + 2][lr] = wv.z; Ws[lc + 3][lr] = wv.w;
        __syncthreads();
        #pragma unroll
        for (int k = 0; k < 16; k++) {
            float4 a = *(const float4*)&As[k][ty * 4];
            float4 b = *(const float4*)&Ws[k][tx * 4];
            acc[0][0] = fmaf(a.x, b.x, acc[0][0]); acc[0][1] = fmaf(a.x, b.y, acc[0][1]);
            acc[0][2] = fmaf(a.x, b.z, acc[0][2]); acc[0][3] = fmaf(a.x, b.w, acc[0][3]);
            acc[1][0] = fmaf(a.y, b.x, acc[1][0]); acc[1][1] = fmaf(a.y, b.y, acc[1][1]);
            acc[1][2] = fmaf(a.y, b.z, acc[1][2]); acc[1][3] = fmaf(a.y, b.w, acc[1][3]);
            acc[2][0] = fmaf(a.z, b.x, acc[2][0]); acc[2][1] = fmaf(a.z, b.y, acc[2][1]);
            acc[2][2] = fmaf(a.z, b.z, acc[2][2]); acc[2][3] = fmaf(a.z, b.w, acc[2][3]);
            acc[3][0] = fmaf(a.w, b.x, acc[3][0]); acc[3][1] = fmaf(a.w, b.y, acc[3][1]);
            acc[3][2] = fmaf(a.w, b.z, acc[3][2]); acc[3][3] = fmaf(a.w, b.w, acc[3][3]);
        }
        __syncthreads();
    }

    const int col = n0 + tx * 4;
    if (col < Nout) {
        float bx = 0.f, by = 0.f, bz = 0.f, bw = 0.f;
        if (bias) { bx = bias[col]; by = bias[col + 1]; bz = bias[col + 2]; bw = bias[col + 3]; }
        #pragma unroll
        for (int i = 0; i < 4; i++) {
            int row = m0 + ty * 4 + i;
            float4 v = make_float4(acc[i][0] + bx, acc[i][1] + by,
                                   acc[i][2] + bz, acc[i][3] + bw);
            if (doRelu) {
                v.x = fmaxf(v.x, 0.f); v.y = fmaxf(v.y, 0.f);
                v.z = fmaxf(v.z, 0.f); v.w = fmaxf(v.w, 0.f);
            }
            *(float4*)&C[(size_t)row * Nout + col] = v;
        }
    }
}

// ---------------- attention scores: warp per (node, head) -------------------
__global__ void attn_scores_kernel(const float* __restrict__ att_src,
                                   const float* __restrict__ att_dst) {
    int gw = (blockIdx.x * blockDim.x + threadIdx.x) >> 5;
    int lane = threadIdx.x & 31;
    if (gw >= N_NODES * HEADS) return;
    int node = gw >> 1, head = gw & 1;
    const float* hp = g_h + (size_t)node * F_DIM + head * OUT_CH + lane * 8;
    const float* sp = att_src + head * OUT_CH + lane * 8;
    const float* dp = att_dst + head * OUT_CH + lane * 8;
    float4 h0 = *(const float4*)hp,       h1 = *(const float4*)(hp + 4);
    float4 s0 = *(const float4*)sp,       s1 = *(const float4*)(sp + 4);
    float4 d0 = *(const float4*)dp,       d1 = *(const float4*)(dp + 4);
    float s = h0.x * s0.x + h0.y * s0.y + h0.z * s0.z + h0.w * s0.w
            + h1.x * s1.x + h1.y * s1.y + h1.z * s1.z + h1.w * s1.w;
    float d = h0.x * d0.x + h0.y * d0.y + h0.z * d0.z + h0.w * d0.w
            + h1.x * d1.x + h1.y * d1.y + h1.z * d1.z + h1.w * d1.w;
    #pragma unroll
    for (int o = 16; o; o >>= 1) {
        s += __shfl_xor_sync(0xffffffffu, s, o);
        d += __shfl_xor_sync(0xffffffffu, d, o);
    }
    if (lane == 0) { g_as[gw] = s; g_ad[gw] = d; }
}

// ---------------- edge pass 1: segment max ----------------------------------
__global__ void edge_max_kernel(const void* __restrict__ ei) {
    int e = blockIdx.x * blockDim.x + threadIdx.x;
    if (e >= E_TOT) return;
    int src, dst; edge_nodes(ei, e, src, dst);
    #pragma unroll
    for (int h = 0; h < HEADS; h++) {
        float v = g_as[src * HEADS + h] + g_ad[dst * HEADS + h];
        v = (v > 0.f) ? v : 0.2f * v;
        atomicMax(&g_emax[dst * HEADS + h], enc_f(v));
    }
}

// ---------------- edge pass 2: exp + segment sum -----------------------------
__global__ void edge_exp_kernel(const void* __restrict__ ei) {
    int e = blockIdx.x * blockDim.x + threadIdx.x;
    if (e >= E_TOT) return;
    int src, dst; edge_nodes(ei, e, src, dst);
    #pragma unroll
    for (int h = 0; h < HEADS; h++) {
        float v = g_as[src * HEADS + h] + g_ad[dst * HEADS + h];
        v = (v > 0.f) ? v : 0.2f * v;
        float m = dec_f(g_emax[dst * HEADS + h]);
        float w = expf(v - m);
        g_w[e * HEADS + h] = w;
        atomicAdd(&g_esum[dst * HEADS + h], w);
    }
}

// ---------------- edge pass 3: aggregate alpha * h[src] -> out[dst] ---------
__global__ void edge_agg_kernel(const void* __restrict__ ei) {
    int gw = (blockIdx.x * blockDim.x + threadIdx.x) >> 5;
    int lane = threadIdx.x & 31;
    if (gw >= E_TOT * HEADS) return;
    int e = gw >> 1, head = gw & 1;
    int src, dst; edge_nodes(ei, e, src, dst);
    float alpha = g_w[e * HEADS + head] / g_esum[dst * HEADS + head];
    const float* hp = g_h   + (size_t)src * F_DIM + head * OUT_CH + lane * 8;
    float*       op = g_gat + (size_t)dst * F_DIM + head * OUT_CH + lane * 8;
    float4 v0 = *(const float4*)hp, v1 = *(const float4*)(hp + 4);
    atomicAdd(op + 0, alpha * v0.x); atomicAdd(op + 1, alpha * v0.y);
    atomicAdd(op + 2, alpha * v0.z); atomicAdd(op + 3, alpha * v0.w);
    atomicAdd(op + 4, alpha * v1.x); atomicAdd(op + 5, alpha * v1.y);
    atomicAdd(op + 6, alpha * v1.z); atomicAdd(op + 7, alpha * v1.w);
}

// ---------------- bias + relu on GAT output ---------------------------------
__global__ void bias_relu_kernel(const float* __restrict__ conv_b) {
    int i = blockIdx.x * blockDim.x + threadIdx.x;
    if (i >= N_NODES * F_DIM / 4) return;
    float4 v = ((float4*)g_gat)[i];
    int col = (i * 4) & (F_DIM - 1);
    v.x = fmaxf(v.x + conv_b[col + 0], 0.f);
    v.y = fmaxf(v.y + conv_b[col + 1], 0.f);
    v.z = fmaxf(v.z + conv_b[col + 2], 0.f);
    v.w = fmaxf(v.w + conv_b[col + 3], 0.f);
    ((float4*)g_gat)[i] = v;
}

// ---------------- last MLP layer: 32 -> 3 (no relu) -------------------------
__global__ __launch_bounds__(256)
void final_layer_kernel(const float* __restrict__ W4, const float* __restrict__ b4) {
    __shared__ float w[3][32];
    __shared__ float bb[3];
    int tid = threadIdx.x;
    if (tid < 96) w[tid / 32][tid & 31] = W4[tid];
    if (tid < 3)  bb[tid] = b4[tid];
    __syncthreads();
    int n = blockIdx.x * blockDim.x + tid;
    if (n >= N_NODES) return;
    const float4* hp = (const float4*)(g_h4 + (size_t)n * 32);
    float a0 = bb[0], a1 = bb[1], a2 = bb[2];
    #pragma unroll
    for (int q = 0; q < 8; q++) {
        float4 v = hp[q];
        a0 = fmaf(v.x, w[0][q*4+0], a0); a0 = fmaf(v.y, w[0][q*4+1], a0);
        a0 = fmaf(v.z, w[0][q*4+2], a0); a0 = fmaf(v.w, w[0][q*4+3], a0);
        a1 = fmaf(v.x, w[1][q*4+0], a1); a1 = fmaf(v.y, w[1][q*4+1], a1);
        a1 = fmaf(v.z, w[1][q*4+2], a1); a1 = fmaf(v.w, w[1][q*4+3], a1);
        a2 = fmaf(v.x, w[2][q*4+0], a2); a2 = fmaf(v.y, w[2][q*4+1], a2);
        a2 = fmaf(v.z, w[2][q*4+2], a2); a2 = fmaf(v.w, w[2][q*4+3], a2);
    }
    float4 out = make_float4(a0, a1, a2, 0.f);
    ((float4*)g_h5)[n] = out;
}

// ---------------- pairwise distances: tile 128x128, FFMA-pipe sqrt ----------
__global__ __launch_bounds__(256)
void cdist_kernel(float* __restrict__ out) {
    __shared__ float4 rp[128];
    __shared__ float4 cp[128];
    int tid = threadIdx.x;
    int rb = blockIdx.y * 128, cb = blockIdx.x * 128;
    if (tid < 128) rp[tid] = ((const float4*)g_h5)[rb + tid];
    else           cp[tid - 128] = ((const float4*)g_h5)[cb + tid - 128];
    __syncthreads();
    int tx = tid & 31, ty = tid >> 5;     // tx: 32 col groups, ty: 8 row groups
    float4 q0 = cp[tx * 4 + 0], q1 = cp[tx * 4 + 1],
           q2 = cp[tx * 4 + 2], q3 = cp[tx * 4 + 3];
    #pragma unroll
    for (int j = 0; j < 16; j++) {
        int r = j * 8 + ty;
        float4 p = rp[r];
        float dx, dy, dz, d2;
        float4 o;
        dx = p.x - q0.x; dy = p.y - q0.y; dz = p.z - q0.z;
        d2 = fmaf(dx, dx, fmaf(dy, dy, dz * dz)); o.x = fast_sqrt(d2);
        dx = p.x - q1.x; dy = p.y - q1.y; dz = p.z - q1.z;
        d2 = fmaf(dx, dx, fmaf(dy, dy, dz * dz)); o.y = fast_sqrt(d2);
        dx = p.x - q2.x; dy = p.y - q2.y; dz = p.z - q2.z;
        d2 = fmaf(dx, dx, fmaf(dy, dy, dz * dz)); o.z = fast_sqrt(d2);
        dx = p.x - q3.x; dy = p.y - q3.y; dz = p.z - q3.z;
        d2 = fmaf(dx, dx, fmaf(dy, dy, dz * dz)); o.w = fast_sqrt(d2);
        *(float4*)&out[(size_t)(rb + r) * N_NODES + cb + tx * 4] = o;
    }
}

// ---------------- launch ------------------------------------------------------
extern "C" void kernel_launch(void* const* d_in, const int* in_sizes, int n_in,
                              void* d_out, int out_size) {
    const float*      x       = (const float*)d_in[0];
    const void*       ei      = (const void*)d_in[1];
    const float*      conv_W  = (const float*)d_in[2];
    const float*      att_src = (const float*)d_in[3];
    const float*      att_dst = (const float*)d_in[4];
    const float*      conv_b  = (const float*)d_in[5];
    const float*      Wa = (const float*)d_in[6];  const float* ba = (const float*)d_in[7];
    const float*      W1 = (const float*)d_in[8];  const float* b1 = (const float*)d_in[9];
    const float*      W2 = (const float*)d_in[10]; const float* b2 = (const float*)d_in[11];
    const float*      W3 = (const float*)d_in[12]; const float* b3 = (const float*)d_in[13];
    const float*      W4 = (const float*)d_in[14]; const float* b4 = (const float*)d_in[15];
    float*            out = (float*)d_out;

    // probe edge_index dtype (int64 requested by ref, but JAX x64-off => int32)
    detect_idx_kernel<<<1, 32>>>(ei);

    // zero accumulators (must be repeated every graph replay)
    zero_gat_kernel<<<(N_NODES * F_DIM / 4 + 255) / 256, 256>>>();
    zero_stats_kernel<<<(N_NODES * HEADS + 255) / 256, 256>>>();

    // h = x @ conv_W^T   [16384,512]
    gemm_kernel<<<dim3(F_DIM / 64, N_NODES / 64), 256>>>(
        x, -1, conv_W, nullptr, BUF_H, N_NODES, F_DIM, IN_DIM, 0);

    // attention scores
    attn_scores_kernel<<<(N_NODES * HEADS * 32 + 255) / 256, 256>>>(att_src, att_dst);

    // edge softmax (3 passes)
    int eblk = (E_TOT + 255) / 256;
    edge_max_kernel<<<eblk, 256>>>(ei);
    edge_exp_kernel<<<eblk, 256>>>(ei);
    edge_agg_kernel<<<(E_TOT * HEADS * 32 + 255) / 256, 256>>>(ei);

    // bias + relu on GAT out
    bias_relu_kernel<<<(N_NODES * F_DIM / 4 + 255) / 256, 256>>>(conv_b);

    // MLP
    gemm_kernel<<<dim3(256 / 64, N_NODES / 64), 256>>>(nullptr, BUF_GAT, Wa, ba, BUF_H1, N_NODES, 256, 512, 1);
    gemm_kernel<<<dim3(128 / 64, N_NODES / 64), 256>>>(nullptr, BUF_H1,  W1, b1, BUF_H2, N_NODES, 128, 256, 1);
    gemm_kernel<<<dim3(1,        N_NODES / 64), 256>>>(nullptr, BUF_H2,  W2, b2, BUF_H3, N_NODES, 64, 128, 1);
    gemm_kernel<<<dim3(1,        N_NODES / 64), 256>>>(nullptr, BUF_H3,  W3, b3, BUF_H4, N_NODES, 32, 64, 1);
    final_layer_kernel<<<N_NODES / 256, 256>>>(W4, b4);

    // pairwise distance matrix [16384,16384]
    cdist_kernel<<<dim3(N_NODES / 128, N_NODES / 128), 256>>>(out);
}

// round 4
// speedup vs baseline: 2.7993x; 2.7993x over previous
#include <cuda_runtime.h>
#include <math.h>

#define N_NODES 16384
#define IN_DIM  256
#define HEADS   2
#define OUT_CH  256
#define F_DIM   512
#define E_IN    524288

// ---------------- scratch (device globals) ----------------------------------
__device__ float    g_h   [N_NODES * F_DIM];   // x @ conv_W.T
__device__ float    g_gat [N_NODES * F_DIM];   // GAT output (bias+relu fused)
__device__ float    g_as  [N_NODES * HEADS];
__device__ float    g_ad  [N_NODES * HEADS];
__device__ int      g_deg [N_NODES];           // histogram, then scatter cursor
__device__ int      g_off [N_NODES + 1];       // CSR offsets
__device__ int      g_csr_src[E_IN];           // src node per edge, grouped by dst
__device__ float    g_h1  [N_NODES * 256];
__device__ float    g_h2  [N_NODES * 128];
__device__ float    g_h3  [N_NODES * 64];
__device__ float    g_h4  [N_NODES * 32];
__device__ float    g_h5  [N_NODES * 4];
__device__ int      g_is64;

#define BUF_H   0
#define BUF_GAT 1
#define BUF_H1  2
#define BUF_H2  3
#define BUF_H3  4
#define BUF_H4  5
__device__ __forceinline__ float* buf_ptr(int id) {
    switch (id) {
        case BUF_H:   return g_h;
        case BUF_GAT: return g_gat;
        case BUF_H1:  return g_h1;
        case BUF_H2:  return g_h2;
        case BUF_H3:  return g_h3;
        default:      return g_h4;
    }
}

// ---------------- helpers ---------------------------------------------------
__device__ __forceinline__ float lrelu(float v) { return v > 0.f ? v : 0.2f * v; }

// FFMA-pipe sqrt: magic rsqrt + 2 Newton iters (avoids MUFU throughput wall)
__device__ __forceinline__ float fast_sqrt(float d2) {
    float r = __uint_as_float(0x5f3759dfu - (__float_as_uint(d2) >> 1));
    float hd = 0.5f * d2;
    r = r * fmaf(-(hd * r), r, 1.5f);
    r = r * fmaf(-(hd * r), r, 1.5f);
    return d2 * r;
}

// ---------------- edge_index dtype probe -------------------------------------
__global__ void detect_idx_kernel(const void* __restrict__ ei) {
    if (threadIdx.x == 0 && blockIdx.x == 0) {
        const long long* p = (const long long*)ei;
        int ok64 = 1;
        for (int i = 0; i < 256; i++) {
            long long v = p[i];
            if (v < 0 || v >= N_NODES) { ok64 = 0; break; }
        }
        g_is64 = ok64;
    }
}
__device__ __forceinline__ void edge_nodes(const void* __restrict__ ei, int e,
                                           int& src, int& dst) {
    if (g_is64) {
        const long long* p = (const long long*)ei;
        src = (int)p[e]; dst = (int)p[E_IN + e];
    } else {
        const int* p = (const int*)ei;
        src = p[e]; dst = p[E_IN + e];
    }
    src = min(max(src, 0), N_NODES - 1);
    dst = min(max(dst, 0), N_NODES - 1);
}

// ---------------- CSR build ---------------------------------------------------
__global__ void zero_deg_kernel() {
    int i = blockIdx.x * blockDim.x + threadIdx.x;
    if (i < N_NODES) g_deg[i] = 0;
}
__global__ void hist_kernel(const void* __restrict__ ei) {
    int e = blockIdx.x * blockDim.x + threadIdx.x;
    if (e >= E_IN) return;
    int src, dst; edge_nodes(ei, e, src, dst);
    atomicAdd(&g_deg[dst], 1);
}
__global__ __launch_bounds__(1024)
void scan_kernel() {
    __shared__ int part[1024];
    int t = threadIdx.x;
    int base = t * 16;
    int local[16];
    int s = 0;
    #pragma unroll
    for (int i = 0; i < 16; i++) { local[i] = s; s += g_deg[base + i]; }
    part[t] = s;
    __syncthreads();
    for (int d = 1; d < 1024; d <<= 1) {
        int v = (t >= d) ? part[t - d] : 0;
        __syncthreads();
        part[t] += v;
        __syncthreads();
    }
    int prefix = (t == 0) ? 0 : part[t - 1];
    #pragma unroll
    for (int i = 0; i < 16; i++) {
        int o = prefix + local[i];
        g_off[base + i] = o;
        g_deg[base + i] = o;      // reuse as scatter cursor
    }
    if (t == 1023) g_off[N_NODES] = E_IN;
}
__global__ void scatter_kernel(const void* __restrict__ ei) {
    int e = blockIdx.x * blockDim.x + threadIdx.x;
    if (e >= E_IN) return;
    int src, dst; edge_nodes(ei, e, src, dst);
    int pos = atomicAdd(&g_deg[dst], 1);
    g_csr_src[pos] = src;
}

// ---------------- tiled fp32 GEMM: C = act(A @ W^T + b) ----------------------
__global__ __launch_bounds__(256)
void gemm_kernel(const float* __restrict__ a_raw, int a_id,
                 const float* __restrict__ W, const float* __restrict__ bias,
                 int c_id, int M, int Nout, int K, int doRelu) {
    const float* A = a_raw ? a_raw : (const float*)buf_ptr(a_id);
    float* C = buf_ptr(c_id);

    __shared__ float As[16][64];
    __shared__ float Ws[16][64];
    const int tid = threadIdx.x;
    const int tx = tid & 15, ty = tid >> 4;
    const int m0 = blockIdx.y * 64;
    const int n0 = blockIdx.x * 64;
    const int lr = tid >> 2;
    const int lc = (tid & 3) * 4;

    float acc[4][4];
    #pragma unroll
    for (int i = 0; i < 4; i++)
        #pragma unroll
        for (int j = 0; j < 4; j++) acc[i][j] = 0.f;

    for (int kt = 0; kt < K; kt += 16) {
        float4 av = *(const float4*)&A[(size_t)(m0 + lr) * K + kt + lc];
        As[lc + 0][lr] = av.x; As[lc + 1][lr] = av.y;
        As[lc + 2][lr] = av.z; As[lc + 3][lr] = av.w;
        float4 wv = make_float4(0.f, 0.f, 0.f, 0.f);
        if (n0 + lr < Nout)
            wv = *(const float4*)&W[(size_t)(n0 + lr) * K + kt + lc];
        Ws[lc + 0][lr] = wv.x; Ws[lc + 1][lr] = wv.y;
        Ws[lc + 2][lr] = wv.z; Ws[lc + 3][lr] = wv.w;
        __syncthreads();
        #pragma unroll
        for (int k = 0; k < 16; k++) {
            float4 a = *(const float4*)&As[k][ty * 4];
            float4 b = *(const float4*)&Ws[k][tx * 4];
            acc[0][0] = fmaf(a.x, b.x, acc[0][0]); acc[0][1] = fmaf(a.x, b.y, acc[0][1]);
            acc[0][2] = fmaf(a.x, b.z, acc[0][2]); acc[0][3] = fmaf(a.x, b.w, acc[0][3]);
            acc[1][0] = fmaf(a.y, b.x, acc[1][0]); acc[1][1] = fmaf(a.y, b.y, acc[1][1]);
            acc[1][2] = fmaf(a.y, b.z, acc[1][2]); acc[1][3] = fmaf(a.y, b.w, acc[1][3]);
            acc[2][0] = fmaf(a.z, b.x, acc[2][0]); acc[2][1] = fmaf(a.z, b.y, acc[2][1]);
            acc[2][2] = fmaf(a.z, b.z, acc[2][2]); acc[2][3] = fmaf(a.z, b.w, acc[2][3]);
            acc[3][0] = fmaf(a.w, b.x, acc[3][0]); acc[3][1] = fmaf(a.w, b.y, acc[3][1]);
            acc[3][2] = fmaf(a.w, b.z, acc[3][2]); acc[3][3] = fmaf(a.w, b.w, acc[3][3]);
        }
        __syncthreads();
    }

    const int col = n0 + tx * 4;
    if (col < Nout) {
        float bx = 0.f, by = 0.f, bz = 0.f, bw = 0.f;
        if (bias) { bx = bias[col]; by = bias[col + 1]; bz = bias[col + 2]; bw = bias[col + 3]; }
        #pragma unroll
        for (int i = 0; i < 4; i++) {
            int row = m0 + ty * 4 + i;
            float4 v = make_float4(acc[i][0] + bx, acc[i][1] + by,
                                   acc[i][2] + bz, acc[i][3] + bw);
            if (doRelu) {
                v.x = fmaxf(v.x, 0.f); v.y = fmaxf(v.y, 0.f);
                v.z = fmaxf(v.z, 0.f); v.w = fmaxf(v.w, 0.f);
            }
            *(float4*)&C[(size_t)row * Nout + col] = v;
        }
    }
}

// ---------------- attention scores: warp per (node, head) --------------------
__global__ void attn_scores_kernel(const float* __restrict__ att_src,
                                   const float* __restrict__ att_dst) {
    int gw = (blockIdx.x * blockDim.x + threadIdx.x) >> 5;
    int lane = threadIdx.x & 31;
    if (gw >= N_NODES * HEADS) return;
    int node = gw >> 1, head = gw & 1;
    const float* hp = g_h + (size_t)node * F_DIM + head * OUT_CH + lane * 8;
    const float* sp = att_src + head * OUT_CH + lane * 8;
    const float* dp = att_dst + head * OUT_CH + lane * 8;
    float4 h0 = *(const float4*)hp,       h1 = *(const float4*)(hp + 4);
    float4 s0 = *(const float4*)sp,       s1 = *(const float4*)(sp + 4);
    float4 d0 = *(const float4*)dp,       d1 = *(const float4*)(dp + 4);
    float s = h0.x * s0.x + h0.y * s0.y + h0.z * s0.z + h0.w * s0.w
            + h1.x * s1.x + h1.y * s1.y + h1.z * s1.z + h1.w * s1.w;
    float d = h0.x * d0.x + h0.y * d0.y + h0.z * d0.z + h0.w * d0.w
            + h1.x * d1.x + h1.y * d1.y + h1.z * d1.z + h1.w * d1.w;
    #pragma unroll
    for (int o = 16; o; o >>= 1) {
        s += __shfl_xor_sync(0xffffffffu, s, o);
        d += __shfl_xor_sync(0xffffffffu, d, o);
    }
    if (lane == 0) { g_as[gw] = s; g_ad[gw] = d; }
}

// ---------------- fused GAT: softmax + aggregate + bias + relu ---------------
// one block (128 threads) per dst node; no atomics.
__global__ __launch_bounds__(128)
void gat_agg_kernel(const float* __restrict__ conv_b) {
    const int dst = blockIdx.x;
    const int t = threadIdx.x;
    __shared__ float red[128];
    __shared__ float sh_a0[128], sh_a1[128];
    __shared__ int   sh_src[128];
    __shared__ float sm0, sm1, ss0, ss1;

    const int off = g_off[dst];
    const int deg = g_off[dst + 1] - off;
    const float ad0 = g_ad[dst * 2], ad1 = g_ad[dst * 2 + 1];
    const float self0 = lrelu(g_as[dst * 2] + ad0);
    const float self1 = lrelu(g_as[dst * 2 + 1] + ad1);

    // --- segment max (self-loop included) ---
    float m0 = self0, m1 = self1;
    for (int j = t; j < deg; j += 128) {
        int s = g_csr_src[off + j];
        m0 = fmaxf(m0, lrelu(g_as[s * 2] + ad0));
        m1 = fmaxf(m1, lrelu(g_as[s * 2 + 1] + ad1));
    }
    red[t] = m0; __syncthreads();
    for (int d = 64; d; d >>= 1) { if (t < d) red[t] = fmaxf(red[t], red[t + d]); __syncthreads(); }
    if (t == 0) sm0 = red[0];
    __syncthreads();
    red[t] = m1; __syncthreads();
    for (int d = 64; d; d >>= 1) { if (t < d) red[t] = fmaxf(red[t], red[t + d]); __syncthreads(); }
    if (t == 0) sm1 = red[0];
    __syncthreads();
    m0 = sm0; m1 = sm1;

    // --- segment sum of exp ---
    float s0 = (t == 0) ? expf(self0 - m0) : 0.f;
    float s1 = (t == 0) ? expf(self1 - m1) : 0.f;
    for (int j = t; j < deg; j += 128) {
        int s = g_csr_src[off + j];
        s0 += expf(lrelu(g_as[s * 2] + ad0) - m0);
        s1 += expf(lrelu(g_as[s * 2 + 1] + ad1) - m1);
    }
    red[t] = s0; __syncthreads();
    for (int d = 64; d; d >>= 1) { if (t < d) red[t] += red[t + d]; __syncthreads(); }
    if (t == 0) ss0 = red[0];
    __syncthreads();
    red[t] = s1; __syncthreads();
    for (int d = 64; d; d >>= 1) { if (t < d) red[t] += red[t + d]; __syncthreads(); }
    if (t == 0) ss1 = red[0];
    __syncthreads();
    const float rs0 = 1.f / ss0, rs1 = 1.f / ss1;

    // --- accumulate alpha * h[src] ---
    const int head = t >> 6;                       // 0 or 1 (columns t*4 in [0,512))
    const float mself  = head ? self1 : self0;
    const float mmax   = head ? sm1 : sm0;
    const float rss    = head ? rs1 : rs0;
    const float a_self = expf(mself - mmax) * rss;

    float4 v = *(const float4*)&g_h[(size_t)dst * F_DIM + t * 4];
    float4 acc = make_float4(a_self * v.x, a_self * v.y, a_self * v.z, a_self * v.w);

    for (int c = 0; c < deg; c += 128) {
        int j = c + t;
        if (j < deg) {
            int s = g_csr_src[off + j];
            sh_src[t] = s;
            sh_a0[t] = expf(lrelu(g_as[s * 2] + ad0) - sm0) * rs0;
            sh_a1[t] = expf(lrelu(g_as[s * 2 + 1] + ad1) - sm1) * rs1;
        }
        __syncthreads();
        int cnt = min(128, deg - c);
        for (int j2 = 0; j2 < cnt; j2++) {
            const float4 hv = *(const float4*)&g_h[(size_t)sh_src[j2] * F_DIM + t * 4];
            float a = head ? sh_a1[j2] : sh_a0[j2];
            acc.x = fmaf(a, hv.x, acc.x);
            acc.y = fmaf(a, hv.y, acc.y);
            acc.z = fmaf(a, hv.z, acc.z);
            acc.w = fmaf(a, hv.w, acc.w);
        }
        __syncthreads();
    }

    // --- fused bias + relu ---
    float4 b = *(const float4*)&conv_b[t * 4];
    acc.x = fmaxf(acc.x + b.x, 0.f);
    acc.y = fmaxf(acc.y + b.y, 0.f);
    acc.z = fmaxf(acc.z + b.z, 0.f);
    acc.w = fmaxf(acc.w + b.w, 0.f);
    *(float4*)&g_gat[(size_t)dst * F_DIM + t * 4] = acc;
}

// ---------------- last MLP layer: 32 -> 3 (no relu) --------------------------
__global__ __launch_bounds__(256)
void final_layer_kernel(const float* __restrict__ W4, const float* __restrict__ b4) {
    __shared__ float w[3][32];
    __shared__ float bb[3];
    int tid = threadIdx.x;
    if (tid < 96) w[tid / 32][tid & 31] = W4[tid];
    if (tid < 3)  bb[tid] = b4[tid];
    __syncthreads();
    int n = blockIdx.x * blockDim.x + tid;
    if (n >= N_NODES) return;
    const float4* hp = (const float4*)(g_h4 + (size_t)n * 32);
    float a0 = bb[0], a1 = bb[1], a2 = bb[2];
    #pragma unroll
    for (int q = 0; q < 8; q++) {
        float4 v = hp[q];
        a0 = fmaf(v.x, w[0][q*4+0], a0); a0 = fmaf(v.y, w[0][q*4+1], a0);
        a0 = fmaf(v.z, w[0][q*4+2], a0); a0 = fmaf(v.w, w[0][q*4+3], a0);
        a1 = fmaf(v.x, w[1][q*4+0], a1); a1 = fmaf(v.y, w[1][q*4+1], a1);
        a1 = fmaf(v.z, w[1][q*4+2], a1); a1 = fmaf(v.w, w[1][q*4+3], a1);
        a2 = fmaf(v.x, w[2][q*4+0], a2); a2 = fmaf(v.y, w[2][q*4+1], a2);
        a2 = fmaf(v.z, w[2][q*4+2], a2); a2 = fmaf(v.w, w[2][q*4+3], a2);
    }
    ((float4*)g_h5)[n] = make_float4(a0, a1, a2, 0.f);
}

// ---------------- pairwise distances ------------------------------------------
__global__ __launch_bounds__(256)
void cdist_kernel(float* __restrict__ out) {
    __shared__ float4 rp[128];
    __shared__ float4 cp[128];
    int tid = threadIdx.x;
    int rb = blockIdx.y * 128, cb = blockIdx.x * 128;
    if (tid < 128) rp[tid] = ((const float4*)g_h5)[rb + tid];
    else           cp[tid - 128] = ((const float4*)g_h5)[cb + tid - 128];
    __syncthreads();
    int tx = tid & 31, ty = tid >> 5;
    float4 q0 = cp[tx * 4 + 0], q1 = cp[tx * 4 + 1],
           q2 = cp[tx * 4 + 2], q3 = cp[tx * 4 + 3];
    #pragma unroll
    for (int j = 0; j < 16; j++) {
        int r = j * 8 + ty;
        float4 p = rp[r];
        float dx, dy, dz, d2;
        float4 o;
        dx = p.x - q0.x; dy = p.y - q0.y; dz = p.z - q0.z;
        d2 = fmaf(dx, dx, fmaf(dy, dy, dz * dz)); o.x = fast_sqrt(d2);
        dx = p.x - q1.x; dy = p.y - q1.y; dz = p.z - q1.z;
        d2 = fmaf(dx, dx, fmaf(dy, dy, dz * dz)); o.y = fast_sqrt(d2);
        dx = p.x - q2.x; dy = p.y - q2.y; dz = p.z - q2.z;
        d2 = fmaf(dx, dx, fmaf(dy, dy, dz * dz)); o.z = fast_sqrt(d2);
        dx = p.x - q3.x; dy = p.y - q3.y; dz = p.z - q3.z;
        d2 = fmaf(dx, dx, fmaf(dy, dy, dz * dz)); o.w = fast_sqrt(d2);
        *(float4*)&out[(size_t)(rb + r) * N_NODES + cb + tx * 4] = o;
    }
}

// ---------------- launch -------------------------------------------------------
extern "C" void kernel_launch(void* const* d_in, const int* in_sizes, int n_in,
                              void* d_out, int out_size) {
    const float* x       = (const float*)d_in[0];
    const void*  ei      = (const void*)d_in[1];
    const float* conv_W  = (const float*)d_in[2];
    const float* att_src = (const float*)d_in[3];
    const float* att_dst = (const float*)d_in[4];
    const float* conv_b  = (const float*)d_in[5];
    const float* Wa = (const float*)d_in[6];  const float* ba = (const float*)d_in[7];
    const float* W1 = (const float*)d_in[8];  const float* b1 = (const float*)d_in[9];
    const float* W2 = (const float*)d_in[10]; const float* b2 = (const float*)d_in[11];
    const float* W3 = (const float*)d_in[12]; const float* b3 = (const float*)d_in[13];
    const float* W4 = (const float*)d_in[14]; const float* b4 = (const float*)d_in[15];
    float*       out = (float*)d_out;

    detect_idx_kernel<<<1, 32>>>(ei);

    // CSR build (per replay; edge data is constant but we must be stateless)
    zero_deg_kernel<<<(N_NODES + 255) / 256, 256>>>();
    hist_kernel<<<(E_IN + 255) / 256, 256>>>(ei);
    scan_kernel<<<1, 1024>>>();
    scatter_kernel<<<(E_IN + 255) / 256, 256>>>(ei);

    // h = x @ conv_W^T
    gemm_kernel<<<dim3(F_DIM / 64, N_NODES / 64), 256>>>(
        x, -1, conv_W, nullptr, BUF_H, N_NODES, F_DIM, IN_DIM, 0);

    attn_scores_kernel<<<(N_NODES * HEADS * 32 + 255) / 256, 256>>>(att_src, att_dst);

    // fused softmax + aggregation + bias + relu
    gat_agg_kernel<<<N_NODES, 128>>>(conv_b);

    // MLP
    gemm_kernel<<<dim3(256 / 64, N_NODES / 64), 256>>>(nullptr, BUF_GAT, Wa, ba, BUF_H1, N_NODES, 256, 512, 1);
    gemm_kernel<<<dim3(128 / 64, N_NODES / 64), 256>>>(nullptr, BUF_H1,  W1, b1, BUF_H2, N_NODES, 128, 256, 1);
    gemm_kernel<<<dim3(1,        N_NODES / 64), 256>>>(nullptr, BUF_H2,  W2, b2, BUF_H3, N_NODES, 64, 128, 1);
    gemm_kernel<<<dim3(1,        N_NODES / 64), 256>>>(nullptr, BUF_H3,  W3, b3, BUF_H4, N_NODES, 32, 64, 1);
    final_layer_kernel<<<N_NODES / 256, 256>>>(W4, b4);

    cdist_kernel<<<dim3(N_NODES / 128, N_NODES / 128), 256>>>(out);
}

// round 5
// speedup vs baseline: 3.0134x; 1.0765x over previous
#include <cuda_runtime.h>
#include <math.h>

#define N_NODES 16384
#define IN_DIM  256
#define HEADS   2
#define OUT_CH  256
#define F_DIM   512
#define E_IN    524288

// ---------------- scratch (device globals) ----------------------------------
__device__ float    g_h   [N_NODES * F_DIM];
__device__ float    g_gat [N_NODES * F_DIM];
__device__ float    g_as  [N_NODES * HEADS];
__device__ float    g_ad  [N_NODES * HEADS];
__device__ int      g_deg [N_NODES];
__device__ int      g_off [N_NODES + 1];
__device__ int      g_csr_src[E_IN];
__device__ float    g_h1  [N_NODES * 256];
__device__ float    g_h2  [N_NODES * 128];
__device__ float    g_h3  [N_NODES * 64];
__device__ float    g_h4  [N_NODES * 32];
__device__ float    g_h5  [N_NODES * 4];
__device__ int      g_is64;

#define BUF_H   0
#define BUF_GAT 1
#define BUF_H1  2
#define BUF_H2  3
#define BUF_H3  4
#define BUF_H4  5
__device__ __forceinline__ float* buf_ptr(int id) {
    switch (id) {
        case BUF_H:   return g_h;
        case BUF_GAT: return g_gat;
        case BUF_H1:  return g_h1;
        case BUF_H2:  return g_h2;
        case BUF_H3:  return g_h3;
        default:      return g_h4;
    }
}

// ---------------- helpers ---------------------------------------------------
__device__ __forceinline__ float lrelu(float v) { return v > 0.f ? v : 0.2f * v; }

__device__ __forceinline__ float fast_sqrt(float d2) {
    float r = __uint_as_float(0x5f3759dfu - (__float_as_uint(d2) >> 1));
    float hd = 0.5f * d2;
    r = r * fmaf(-(hd * r), r, 1.5f);
    r = r * fmaf(-(hd * r), r, 1.5f);
    return d2 * r;
}

// ---------------- edge_index dtype probe -------------------------------------
__global__ void detect_idx_kernel(const void* __restrict__ ei) {
    if (threadIdx.x == 0 && blockIdx.x == 0) {
        const long long* p = (const long long*)ei;
        int ok64 = 1;
        for (int i = 0; i < 256; i++) {
            long long v = p[i];
            if (v < 0 || v >= N_NODES) { ok64 = 0; break; }
        }
        g_is64 = ok64;
    }
}
__device__ __forceinline__ void edge_nodes(const void* __restrict__ ei, int e,
                                           int& src, int& dst) {
    if (g_is64) {
        const long long* p = (const long long*)ei;
        src = (int)p[e]; dst = (int)p[E_IN + e];
    } else {
        const int* p = (const int*)ei;
        src = p[e]; dst = p[E_IN + e];
    }
    src = min(max(src, 0), N_NODES - 1);
    dst = min(max(dst, 0), N_NODES - 1);
}

// ---------------- CSR build ---------------------------------------------------
__global__ void zero_deg_kernel() {
    int i = blockIdx.x * blockDim.x + threadIdx.x;
    if (i < N_NODES) g_deg[i] = 0;
}
__global__ void hist_kernel(const void* __restrict__ ei) {
    int e = blockIdx.x * blockDim.x + threadIdx.x;
    if (e >= E_IN) return;
    int src, dst; edge_nodes(ei, e, src, dst);
    atomicAdd(&g_deg[dst], 1);
}
// shuffle-based single-block scan over 16384 ints (16 per thread)
__global__ __launch_bounds__(1024)
void scan_kernel() {
    __shared__ int wsum[32];
    int t = threadIdx.x;
    int base = t * 16;
    int local[16];
    int s = 0;
    #pragma unroll
    for (int i = 0; i < 16; i++) { local[i] = s; s += g_deg[base + i]; }
    int lane = t & 31, warp = t >> 5;
    int inc = s;
    #pragma unroll
    for (int d = 1; d < 32; d <<= 1) {
        int v = __shfl_up_sync(0xffffffffu, inc, d);
        if (lane >= d) inc += v;
    }
    if (lane == 31) wsum[warp] = inc;
    __syncthreads();
    if (warp == 0) {
        int v = wsum[lane];
        #pragma unroll
        for (int d = 1; d < 32; d <<= 1) {
            int u = __shfl_up_sync(0xffffffffu, v, d);
            if (lane >= d) v += u;
        }
        wsum[lane] = v;
    }
    __syncthreads();
    int prefix = (warp ? wsum[warp - 1] : 0) + (inc - s);
    #pragma unroll
    for (int i = 0; i < 16; i++) {
        int o = prefix + local[i];
        g_off[base + i] = o;
        g_deg[base + i] = o;        // reuse as scatter cursor
    }
    if (t == 1023) g_off[N_NODES] = E_IN;
}
__global__ void scatter_kernel(const void* __restrict__ ei) {
    int e = blockIdx.x * blockDim.x + threadIdx.x;
    if (e >= E_IN) return;
    int src, dst; edge_nodes(ei, e, src, dst);
    int pos = atomicAdd(&g_deg[dst], 1);
    g_csr_src[pos] = src;
}

// ---------------- big GEMM: 128x128 tile, 8x8 microtile ----------------------
// requires M%128==0, Nout%128==0, K%16==0
__global__ __launch_bounds__(256)
void gemm128_kernel(const float* __restrict__ a_raw, int a_id,
                    const float* __restrict__ W, const float* __restrict__ bias,
                    int c_id, int Nout, int K, int doRelu) {
    const float* A = a_raw ? a_raw : (const float*)buf_ptr(a_id);
    float* C = buf_ptr(c_id);

    __shared__ float As[16][128];
    __shared__ float Ws[16][128];
    const int tid = threadIdx.x;
    const int tx = tid & 15, ty = tid >> 4;
    const int m0 = blockIdx.y * 128;
    const int n0 = blockIdx.x * 128;

    float acc[8][8];
    #pragma unroll
    for (int i = 0; i < 8; i++)
        #pragma unroll
        for (int j = 0; j < 8; j++) acc[i][j] = 0.f;

    for (int kt = 0; kt < K; kt += 16) {
        #pragma unroll
        for (int u = 0; u < 2; u++) {
            int s = tid * 2 + u;                 // 0..511
            int row = s >> 2, c4 = (s & 3) * 4;
            float4 v = *(const float4*)&A[(size_t)(m0 + row) * K + kt + c4];
            As[c4 + 0][row] = v.x; As[c4 + 1][row] = v.y;
            As[c4 + 2][row] = v.z; As[c4 + 3][row] = v.w;
            float4 w = *(const float4*)&W[(size_t)(n0 + row) * K + kt + c4];
            Ws[c4 + 0][row] = w.x; Ws[c4 + 1][row] = w.y;
            Ws[c4 + 2][row] = w.z; Ws[c4 + 3][row] = w.w;
        }
        __syncthreads();
        #pragma unroll
        for (int k = 0; k < 16; k++) {
            float4 a0 = *(const float4*)&As[k][ty * 8];
            float4 a1 = *(const float4*)&As[k][ty * 8 + 4];
            float4 b0 = *(const float4*)&Ws[k][tx * 8];
            float4 b1 = *(const float4*)&Ws[k][tx * 8 + 4];
            float av[8] = {a0.x, a0.y, a0.z, a0.w, a1.x, a1.y, a1.z, a1.w};
            float bv[8] = {b0.x, b0.y, b0.z, b0.w, b1.x, b1.y, b1.z, b1.w};
            #pragma unroll
            for (int i = 0; i < 8; i++)
                #pragma unroll
                for (int j = 0; j < 8; j++)
                    acc[i][j] = fmaf(av[i], bv[j], acc[i][j]);
        }
        __syncthreads();
    }

    const int col = n0 + tx * 8;
    float bv[8];
    #pragma unroll
    for (int j = 0; j < 8; j++) bv[j] = bias ? bias[col + j] : 0.f;
    #pragma unroll
    for (int i = 0; i < 8; i++) {
        int row = m0 + ty * 8 + i;
        float o[8];
        #pragma unroll
        for (int j = 0; j < 8; j++) {
            o[j] = acc[i][j] + bv[j];
            if (doRelu) o[j] = fmaxf(o[j], 0.f);
        }
        *(float4*)&C[(size_t)row * Nout + col]     = make_float4(o[0], o[1], o[2], o[3]);
        *(float4*)&C[(size_t)row * Nout + col + 4] = make_float4(o[4], o[5], o[6], o[7]);
    }
}

// ---------------- small GEMM (Nout<128): 64x64 tile, 4x4 microtile -----------
__global__ __launch_bounds__(256)
void gemm_kernel(int a_id, const float* __restrict__ W, const float* __restrict__ bias,
                 int c_id, int Nout, int K, int doRelu) {
    const float* A = (const float*)buf_ptr(a_id);
    float* C = buf_ptr(c_id);

    __shared__ float As[16][64];
    __shared__ float Ws[16][64];
    const int tid = threadIdx.x;
    const int tx = tid & 15, ty = tid >> 4;
    const int m0 = blockIdx.y * 64;
    const int n0 = blockIdx.x * 64;
    const int lr = tid >> 2;
    const int lc = (tid & 3) * 4;

    float acc[4][4];
    #pragma unroll
    for (int i = 0; i < 4; i++)
        #pragma unroll
        for (int j = 0; j < 4; j++) acc[i][j] = 0.f;

    for (int kt = 0; kt < K; kt += 16) {
        float4 av = *(const float4*)&A[(size_t)(m0 + lr) * K + kt + lc];
        As[lc + 0][lr] = av.x; As[lc + 1][lr] = av.y;
        As[lc + 2][lr] = av.z; As[lc + 3][lr] = av.w;
        float4 wv = make_float4(0.f, 0.f, 0.f, 0.f);
        if (n0 + lr < Nout)
            wv = *(const float4*)&W[(size_t)(n0 + lr) * K + kt + lc];
        Ws[lc + 0][lr] = wv.x; Ws[lc + 1][lr] = wv.y;
        Ws[lc + 2][lr] = wv.z; Ws[lc + 3][lr] = wv.w;
        __syncthreads();
        #pragma unroll
        for (int k = 0; k < 16; k++) {
            float4 a = *(const float4*)&As[k][ty * 4];
            float4 b = *(const float4*)&Ws[k][tx * 4];
            acc[0][0] = fmaf(a.x, b.x, acc[0][0]); acc[0][1] = fmaf(a.x, b.y, acc[0][1]);
            acc[0][2] = fmaf(a.x, b.z, acc[0][2]); acc[0][3] = fmaf(a.x, b.w, acc[0][3]);
            acc[1][0] = fmaf(a.y, b.x, acc[1][0]); acc[1][1] = fmaf(a.y, b.y, acc[1][1]);
            acc[1][2] = fmaf(a.y, b.z, acc[1][2]); acc[1][3] = fmaf(a.y, b.w, acc[1][3]);
            acc[2][0] = fmaf(a.z, b.x, acc[2][0]); acc[2][1] = fmaf(a.z, b.y, acc[2][1]);
            acc[2][2] = fmaf(a.z, b.z, acc[2][2]); acc[2][3] = fmaf(a.z, b.w, acc[2][3]);
            acc[3][0] = fmaf(a.w, b.x, acc[3][0]); acc[3][1] = fmaf(a.w, b.y, acc[3][1]);
            acc[3][2] = fmaf(a.w, b.z, acc[3][2]); acc[3][3] = fmaf(a.w, b.w, acc[3][3]);
        }
        __syncthreads();
    }

    const int col = n0 + tx * 4;
    if (col < Nout) {
        float bx = bias[col], by = bias[col + 1], bz = bias[col + 2], bw = bias[col + 3];
        #pragma unroll
        for (int i = 0; i < 4; i++) {
            int row = m0 + ty * 4 + i;
            float4 v = make_float4(acc[i][0] + bx, acc[i][1] + by,
                                   acc[i][2] + bz, acc[i][3] + bw);
            if (doRelu) {
                v.x = fmaxf(v.x, 0.f); v.y = fmaxf(v.y, 0.f);
                v.z = fmaxf(v.z, 0.f); v.w = fmaxf(v.w, 0.f);
            }
            *(float4*)&C[(size_t)row * Nout + col] = v;
        }
    }
}

// ---------------- attention scores: warp per (node, head) --------------------
__global__ void attn_scores_kernel(const float* __restrict__ att_src,
                                   const float* __restrict__ att_dst) {
    int gw = (blockIdx.x * blockDim.x + threadIdx.x) >> 5;
    int lane = threadIdx.x & 31;
    if (gw >= N_NODES * HEADS) return;
    int node = gw >> 1, head = gw & 1;
    const float* hp = g_h + (size_t)node * F_DIM + head * OUT_CH + lane * 8;
    const float* sp = att_src + head * OUT_CH + lane * 8;
    const float* dp = att_dst + head * OUT_CH + lane * 8;
    float4 h0 = *(const float4*)hp,  h1 = *(const float4*)(hp + 4);
    float4 s0 = *(const float4*)sp,  s1 = *(const float4*)(sp + 4);
    float4 d0 = *(const float4*)dp,  d1 = *(const float4*)(dp + 4);
    float s = h0.x * s0.x + h0.y * s0.y + h0.z * s0.z + h0.w * s0.w
            + h1.x * s1.x + h1.y * s1.y + h1.z * s1.z + h1.w * s1.w;
    float d = h0.x * d0.x + h0.y * d0.y + h0.z * d0.z + h0.w * d0.w
            + h1.x * d1.x + h1.y * d1.y + h1.z * d1.z + h1.w * d1.w;
    #pragma unroll
    for (int o = 16; o; o >>= 1) {
        s += __shfl_xor_sync(0xffffffffu, s, o);
        d += __shfl_xor_sync(0xffffffffu, d, o);
    }
    if (lane == 0) { g_as[gw] = s; g_ad[gw] = d; }
}

// ---------------- fused GAT: softmax + aggregate + bias + relu ---------------
__global__ __launch_bounds__(128)
void gat_agg_kernel(const float* __restrict__ conv_b) {
    const int dst = blockIdx.x;
    const int t = threadIdx.x;
    __shared__ float red[128];
    __shared__ float sh_a0[128], sh_a1[128];
    __shared__ int   sh_src[128];
    __shared__ float sm0, sm1, ss0, ss1;

    const int off = g_off[dst];
    const int deg = g_off[dst + 1] - off;
    const float ad0 = g_ad[dst * 2], ad1 = g_ad[dst * 2 + 1];
    const float self0 = lrelu(g_as[dst * 2] + ad0);
    const float self1 = lrelu(g_as[dst * 2 + 1] + ad1);

    float m0 = self0, m1 = self1;
    for (int j = t; j < deg; j += 128) {
        int s = g_csr_src[off + j];
        m0 = fmaxf(m0, lrelu(g_as[s * 2] + ad0));
        m1 = fmaxf(m1, lrelu(g_as[s * 2 + 1] + ad1));
    }
    red[t] = m0; __syncthreads();
    for (int d = 64; d; d >>= 1) { if (t < d) red[t] = fmaxf(red[t], red[t + d]); __syncthreads(); }
    if (t == 0) sm0 = red[0];
    __syncthreads();
    red[t] = m1; __syncthreads();
    for (int d = 64; d; d >>= 1) { if (t < d) red[t] = fmaxf(red[t], red[t + d]); __syncthreads(); }
    if (t == 0) sm1 = red[0];
    __syncthreads();
    m0 = sm0; m1 = sm1;

    float s0 = (t == 0) ? expf(self0 - m0) : 0.f;
    float s1 = (t == 0) ? expf(self1 - m1) : 0.f;
    for (int j = t; j < deg; j += 128) {
        int s = g_csr_src[off + j];
        s0 += expf(lrelu(g_as[s * 2] + ad0) - m0);
        s1 += expf(lrelu(g_as[s * 2 + 1] + ad1) - m1);
    }
    red[t] = s0; __syncthreads();
    for (int d = 64; d; d >>= 1) { if (t < d) red[t] += red[t + d]; __syncthreads(); }
    if (t == 0) ss0 = red[0];
    __syncthreads();
    red[t] = s1; __syncthreads();
    for (int d = 64; d; d >>= 1) { if (t < d) red[t] += red[t + d]; __syncthreads(); }
    if (t == 0) ss1 = red[0];
    __syncthreads();
    const float rs0 = 1.f / ss0, rs1 = 1.f / ss1;

    const int head = t >> 6;
    const float mself  = head ? self1 : self0;
    const float mmax   = head ? sm1 : sm0;
    const float rss    = head ? rs1 : rs0;
    const float a_self = expf(mself - mmax) * rss;

    float4 v = *(const float4*)&g_h[(size_t)dst * F_DIM + t * 4];
    float4 acc = make_float4(a_self * v.x, a_self * v.y, a_self * v.z, a_self * v.w);

    for (int c = 0; c < deg; c += 128) {
        int j = c + t;
        if (j < deg) {
            int s = g_csr_src[off + j];
            sh_src[t] = s;
            sh_a0[t] = expf(lrelu(g_as[s * 2] + ad0) - sm0) * rs0;
            sh_a1[t] = expf(lrelu(g_as[s * 2 + 1] + ad1) - sm1) * rs1;
        }
        __syncthreads();
        int cnt = min(128, deg - c);
        for (int j2 = 0; j2 < cnt; j2++) {
            const float4 hv = *(const float4*)&g_h[(size_t)sh_src[j2] * F_DIM + t * 4];
            float a = head ? sh_a1[j2] : sh_a0[j2];
            acc.x = fmaf(a, hv.x, acc.x);
            acc.y = fmaf(a, hv.y, acc.y);
            acc.z = fmaf(a, hv.z, acc.z);
            acc.w = fmaf(a, hv.w, acc.w);
        }
        __syncthreads();
    }

    float4 b = *(const float4*)&conv_b[t * 4];
    acc.x = fmaxf(acc.x + b.x, 0.f);
    acc.y = fmaxf(acc.y + b.y, 0.f);
    acc.z = fmaxf(acc.z + b.z, 0.f);
    acc.w = fmaxf(acc.w + b.w, 0.f);
    *(float4*)&g_gat[(size_t)dst * F_DIM + t * 4] = acc;
}

// ---------------- last MLP layer: 32 -> 3 ------------------------------------
__global__ __launch_bounds__(256)
void final_layer_kernel(const float* __restrict__ W4, const float* __restrict__ b4) {
    __shared__ float w[3][32];
    __shared__ float bb[3];
    int tid = threadIdx.x;
    if (tid < 96) w[tid / 32][tid & 31] = W4[tid];
    if (tid < 3)  bb[tid] = b4[tid];
    __syncthreads();
    int n = blockIdx.x * blockDim.x + tid;
    if (n >= N_NODES) return;
    const float4* hp = (const float4*)(g_h4 + (size_t)n * 32);
    float a0 = bb[0], a1 = bb[1], a2 = bb[2];
    #pragma unroll
    for (int q = 0; q < 8; q++) {
        float4 v = hp[q];
        a0 = fmaf(v.x, w[0][q*4+0], a0); a0 = fmaf(v.y, w[0][q*4+1], a0);
        a0 = fmaf(v.z, w[0][q*4+2], a0); a0 = fmaf(v.w, w[0][q*4+3], a0);
        a1 = fmaf(v.x, w[1][q*4+0], a1); a1 = fmaf(v.y, w[1][q*4+1], a1);
        a1 = fmaf(v.z, w[1][q*4+2], a1); a1 = fmaf(v.w, w[1][q*4+3], a1);
        a2 = fmaf(v.x, w[2][q*4+0], a2); a2 = fmaf(v.y, w[2][q*4+1], a2);
        a2 = fmaf(v.z, w[2][q*4+2], a2); a2 = fmaf(v.w, w[2][q*4+3], a2);
    }
    ((float4*)g_h5)[n] = make_float4(a0, a1, a2, 0.f);
}

// ---------------- pairwise distances ------------------------------------------
__global__ __launch_bounds__(256)
void cdist_kernel(float* __restrict__ out) {
    __shared__ float4 rp[128];
    __shared__ float4 cp[128];
    int tid = threadIdx.x;
    int rb = blockIdx.y * 128, cb = blockIdx.x * 128;
    if (tid < 128) rp[tid] = ((const float4*)g_h5)[rb + tid];
    else           cp[tid - 128] = ((const float4*)g_h5)[cb + tid - 128];
    __syncthreads();
    int tx = tid & 31, ty = tid >> 5;
    float4 q0 = cp[tx * 4 + 0], q1 = cp[tx * 4 + 1],
           q2 = cp[tx * 4 + 2], q3 = cp[tx * 4 + 3];
    #pragma unroll
    for (int j = 0; j < 16; j++) {
        int r = j * 8 + ty;
        float4 p = rp[r];
        float dx, dy, dz, d2;
        float4 o;
        dx = p.x - q0.x; dy = p.y - q0.y; dz = p.z - q0.z;
        d2 = fmaf(dx, dx, fmaf(dy, dy, dz * dz)); o.x = fast_sqrt(d2);
        dx = p.x - q1.x; dy = p.y - q1.y; dz = p.z - q1.z;
        d2 = fmaf(dx, dx, fmaf(dy, dy, dz * dz)); o.y = fast_sqrt(d2);
        dx = p.x - q2.x; dy = p.y - q2.y; dz = p.z - q2.z;
        d2 = fmaf(dx, dx, fmaf(dy, dy, dz * dz)); o.z = fast_sqrt(d2);
        dx = p.x - q3.x; dy = p.y - q3.y; dz = p.z - q3.z;
        d2 = fmaf(dx, dx, fmaf(dy, dy, dz * dz)); o.w = fast_sqrt(d2);
        *(float4*)&out[(size_t)(rb + r) * N_NODES + cb + tx * 4] = o;
    }
}

// ---------------- launch -------------------------------------------------------
extern "C" void kernel_launch(void* const* d_in, const int* in_sizes, int n_in,
                              void* d_out, int out_size) {
    const float* x       = (const float*)d_in[0];
    const void*  ei      = (const void*)d_in[1];
    const float* conv_W  = (const float*)d_in[2];
    const float* att_src = (const float*)d_in[3];
    const float* att_dst = (const float*)d_in[4];
    const float* conv_b  = (const float*)d_in[5];
    const float* Wa = (const float*)d_in[6];  const float* ba = (const float*)d_in[7];
    const float* W1 = (const float*)d_in[8];  const float* b1 = (const float*)d_in[9];
    const float* W2 = (const float*)d_in[10]; const float* b2 = (const float*)d_in[11];
    const float* W3 = (const float*)d_in[12]; const float* b3 = (const float*)d_in[13];
    const float* W4 = (const float*)d_in[14]; const float* b4 = (const float*)d_in[15];
    float*       out = (float*)d_out;

    detect_idx_kernel<<<1, 32>>>(ei);

    // CSR build
    zero_deg_kernel<<<(N_NODES + 255) / 256, 256>>>();
    hist_kernel<<<(E_IN + 255) / 256, 256>>>(ei);
    scan_kernel<<<1, 1024>>>();
    scatter_kernel<<<(E_IN + 255) / 256, 256>>>(ei);

    // h = x @ conv_W^T   [16384,512]
    gemm128_kernel<<<dim3(F_DIM / 128, N_NODES / 128), 256>>>(
        x, -1, conv_W, nullptr, BUF_H, F_DIM, IN_DIM, 0);

    attn_scores_kernel<<<(N_NODES * HEADS * 32 + 255) / 256, 256>>>(att_src, att_dst);

    gat_agg_kernel<<<N_NODES, 128>>>(conv_b);

    // MLP
    gemm128_kernel<<<dim3(256 / 128, N_NODES / 128), 256>>>(nullptr, BUF_GAT, Wa, ba, BUF_H1, 256, 512, 1);
    gemm128_kernel<<<dim3(1,         N_NODES / 128), 256>>>(nullptr, BUF_H1,  W1, b1, BUF_H2, 128, 256, 1);
    gemm_kernel<<<dim3(1, N_NODES / 64), 256>>>(BUF_H2, W2, b2, BUF_H3, 64, 128, 1);
    gemm_kernel<<<dim3(1, N_NODES / 64), 256>>>(BUF_H3, W3, b3, BUF_H4, 32, 64, 1);
    final_layer_kernel<<<N_NODES / 256, 256>>>(W4, b4);

    cdist_kernel<<<dim3(N_NODES / 128, N_NODES / 128), 256>>>(out);
}

// round 6
// speedup vs baseline: 3.0220x; 1.0029x over previous
#include <cuda_runtime.h>
#include <math.h>

#define N_NODES 16384
#define IN_DIM  256
#define HEADS   2
#define OUT_CH  256
#define F_DIM   512
#define E_IN    524288

// ---------------- scratch (device globals) ----------------------------------
__device__ float    g_h   [N_NODES * F_DIM];
__device__ float    g_gat [N_NODES * F_DIM];
__device__ float    g_as  [N_NODES * HEADS];
__device__ float    g_ad  [N_NODES * HEADS];
__device__ int      g_deg [N_NODES];
__device__ int      g_off [N_NODES + 1];
__device__ int      g_csr_src[E_IN];
__device__ float    g_h1  [N_NODES * 256];
__device__ float    g_h2  [N_NODES * 128];
__device__ float    g_h3  [N_NODES * 64];
__device__ float    g_h4  [N_NODES * 32];
__device__ float    g_h5  [N_NODES * 4];
__device__ int      g_is64;

#define BUF_H   0
#define BUF_GAT 1
#define BUF_H1  2
#define BUF_H2  3
#define BUF_H3  4
#define BUF_H4  5
__device__ __forceinline__ float* buf_ptr(int id) {
    switch (id) {
        case BUF_H:   return g_h;
        case BUF_GAT: return g_gat;
        case BUF_H1:  return g_h1;
        case BUF_H2:  return g_h2;
        case BUF_H3:  return g_h3;
        default:      return g_h4;
    }
}

// ---------------- packed f32x2 helpers ---------------------------------------
__device__ __forceinline__ unsigned long long pack_dup(float a) {
    unsigned long long r;
    asm("mov.b64 %0, {%1, %1};" : "=l"(r) : "f"(a));
    return r;
}
__device__ __forceinline__ void fma_x2(unsigned long long& acc,
                                       unsigned long long a, unsigned long long b) {
    asm("fma.rn.f32x2 %0, %1, %2, %0;" : "+l"(acc) : "l"(a), "l"(b));
}
__device__ __forceinline__ void unpack_x2(unsigned long long v, float& lo, float& hi) {
    asm("mov.b64 {%0, %1}, %2;" : "=f"(lo), "=f"(hi) : "l"(v));
}

// ---------------- helpers ---------------------------------------------------
__device__ __forceinline__ float lrelu(float v) { return v > 0.f ? v : 0.2f * v; }

__device__ __forceinline__ float fast_sqrt(float d2) {
    float r = __uint_as_float(0x5f3759dfu - (__float_as_uint(d2) >> 1));
    float hd = 0.5f * d2;
    r = r * fmaf(-(hd * r), r, 1.5f);
    r = r * fmaf(-(hd * r), r, 1.5f);
    return d2 * r;
}

// ---------------- edge_index dtype probe -------------------------------------
__global__ void detect_idx_kernel(const void* __restrict__ ei) {
    if (threadIdx.x == 0 && blockIdx.x == 0) {
        const long long* p = (const long long*)ei;
        int ok64 = 1;
        for (int i = 0; i < 256; i++) {
            long long v = p[i];
            if (v < 0 || v >= N_NODES) { ok64 = 0; break; }
        }
        g_is64 = ok64;
    }
}
__device__ __forceinline__ void edge_nodes(const void* __restrict__ ei, int e,
                                           int& src, int& dst) {
    if (g_is64) {
        const long long* p = (const long long*)ei;
        src = (int)p[e]; dst = (int)p[E_IN + e];
    } else {
        const int* p = (const int*)ei;
        src = p[e]; dst = p[E_IN + e];
    }
    src = min(max(src, 0), N_NODES - 1);
    dst = min(max(dst, 0), N_NODES - 1);
}

// ---------------- CSR build ---------------------------------------------------
__global__ void zero_deg_kernel() {
    int i = blockIdx.x * blockDim.x + threadIdx.x;
    if (i < N_NODES) g_deg[i] = 0;
}
__global__ void hist_kernel(const void* __restrict__ ei) {
    int e = blockIdx.x * blockDim.x + threadIdx.x;
    if (e >= E_IN) return;
    int src, dst; edge_nodes(ei, e, src, dst);
    atomicAdd(&g_deg[dst], 1);
}
// shuffle-based single-block scan over 16384 ints (16 per thread, int4 I/O)
__global__ __launch_bounds__(1024)
void scan_kernel() {
    __shared__ int wsum[32];
    int t = threadIdx.x;
    int base = t * 16;
    int4 d0 = *(const int4*)&g_deg[base + 0];
    int4 d1 = *(const int4*)&g_deg[base + 4];
    int4 d2 = *(const int4*)&g_deg[base + 8];
    int4 d3 = *(const int4*)&g_deg[base + 12];
    int v0 = d0.x, v1 = d0.y, v2 = d0.z, v3 = d0.w;
    int v4 = d1.x, v5 = d1.y, v6 = d1.z, v7 = d1.w;
    int v8 = d2.x, v9 = d2.y, v10 = d2.z, v11 = d2.w;
    int v12 = d3.x, v13 = d3.y, v14 = d3.z, v15 = d3.w;
    int l0=0, l1=v0, l2=l1+v1, l3=l2+v2, l4=l3+v3, l5=l4+v4, l6=l5+v5, l7=l6+v6,
        l8=l7+v7, l9=l8+v8, l10=l9+v9, l11=l10+v10, l12=l11+v11, l13=l12+v12,
        l14=l13+v13, l15=l14+v14;
    int s = l15 + v15;
    int lane = t & 31, warp = t >> 5;
    int inc = s;
    #pragma unroll
    for (int d = 1; d < 32; d <<= 1) {
        int v = __shfl_up_sync(0xffffffffu, inc, d);
        if (lane >= d) inc += v;
    }
    if (lane == 31) wsum[warp] = inc;
    __syncthreads();
    if (warp == 0) {
        int v = wsum[lane];
        #pragma unroll
        for (int d = 1; d < 32; d <<= 1) {
            int u = __shfl_up_sync(0xffffffffu, v, d);
            if (lane >= d) v += u;
        }
        wsum[lane] = v;
    }
    __syncthreads();
    int p = (warp ? wsum[warp - 1] : 0) + (inc - s);
    int4 o0 = make_int4(p+l0,  p+l1,  p+l2,  p+l3);
    int4 o1 = make_int4(p+l4,  p+l5,  p+l6,  p+l7);
    int4 o2 = make_int4(p+l8,  p+l9,  p+l10, p+l11);
    int4 o3 = make_int4(p+l12, p+l13, p+l14, p+l15);
    *(int4*)&g_off[base + 0]  = o0;  *(int4*)&g_off[base + 4]  = o1;
    *(int4*)&g_off[base + 8]  = o2;  *(int4*)&g_off[base + 12] = o3;
    *(int4*)&g_deg[base + 0]  = o0;  *(int4*)&g_deg[base + 4]  = o1;
    *(int4*)&g_deg[base + 8]  = o2;  *(int4*)&g_deg[base + 12] = o3;
    if (t == 1023) g_off[N_NODES] = E_IN;
}
__global__ void scatter_kernel(const void* __restrict__ ei) {
    int e = blockIdx.x * blockDim.x + threadIdx.x;
    if (e >= E_IN) return;
    int src, dst; edge_nodes(ei, e, src, dst);
    int pos = atomicAdd(&g_deg[dst], 1);
    g_csr_src[pos] = src;
}

// ---------------- big GEMM: 128x128 tile, 8x8 microtile, FFMA2 ---------------
// requires M%128==0, Nout%128==0, K%16==0
__global__ __launch_bounds__(256)
void gemm128_kernel(const float* __restrict__ a_raw, int a_id,
                    const float* __restrict__ W, const float* __restrict__ bias,
                    int c_id, int Nout, int K, int doRelu) {
    const float* A = a_raw ? a_raw : (const float*)buf_ptr(a_id);
    float* C = buf_ptr(c_id);

    __shared__ __align__(16) float As[16][128];
    __shared__ __align__(16) float Ws[16][128];
    const int tid = threadIdx.x;
    const int tx = tid & 15, ty = tid >> 4;
    const int m0 = blockIdx.y * 128;
    const int n0 = blockIdx.x * 128;

    unsigned long long acc[8][4];          // 8 rows x 4 col-pairs, packed f32x2
    #pragma unroll
    for (int i = 0; i < 8; i++)
        #pragma unroll
        for (int j = 0; j < 4; j++) acc[i][j] = 0ull;

    for (int kt = 0; kt < K; kt += 16) {
        #pragma unroll
        for (int u = 0; u < 2; u++) {
            int s = tid * 2 + u;                 // 0..511
            int row = s >> 2, c4 = (s & 3) * 4;
            float4 v = *(const float4*)&A[(size_t)(m0 + row) * K + kt + c4];
            As[c4 + 0][row] = v.x; As[c4 + 1][row] = v.y;
            As[c4 + 2][row] = v.z; As[c4 + 3][row] = v.w;
            float4 w = *(const float4*)&W[(size_t)(n0 + row) * K + kt + c4];
            Ws[c4 + 0][row] = w.x; Ws[c4 + 1][row] = w.y;
            Ws[c4 + 2][row] = w.z; Ws[c4 + 3][row] = w.w;
        }
        __syncthreads();
        #pragma unroll
        for (int k = 0; k < 16; k++) {
            float4 a0 = *(const float4*)&As[k][ty * 8];
            float4 a1 = *(const float4*)&As[k][ty * 8 + 4];
            // B pairs read packed straight from shared (2x 16B loads)
            ulonglong2 bp0 = *(const ulonglong2*)&Ws[k][tx * 8];
            ulonglong2 bp1 = *(const ulonglong2*)&Ws[k][tx * 8 + 4];
            unsigned long long ap[8];
            ap[0] = pack_dup(a0.x); ap[1] = pack_dup(a0.y);
            ap[2] = pack_dup(a0.z); ap[3] = pack_dup(a0.w);
            ap[4] = pack_dup(a1.x); ap[5] = pack_dup(a1.y);
            ap[6] = pack_dup(a1.z); ap[7] = pack_dup(a1.w);
            #pragma unroll
            for (int i = 0; i < 8; i++) {
                fma_x2(acc[i][0], ap[i], bp0.x);
                fma_x2(acc[i][1], ap[i], bp0.y);
                fma_x2(acc[i][2], ap[i], bp1.x);
                fma_x2(acc[i][3], ap[i], bp1.y);
            }
        }
        __syncthreads();
    }

    const int col = n0 + tx * 8;
    float bv[8];
    #pragma unroll
    for (int j = 0; j < 8; j++) bv[j] = bias ? bias[col + j] : 0.f;
    #pragma unroll
    for (int i = 0; i < 8; i++) {
        int row = m0 + ty * 8 + i;
        float o[8];
        #pragma unroll
        for (int j = 0; j < 4; j++) unpack_x2(acc[i][j], o[j * 2], o[j * 2 + 1]);
        #pragma unroll
        for (int j = 0; j < 8; j++) {
            o[j] += bv[j];
            if (doRelu) o[j] = fmaxf(o[j], 0.f);
        }
        *(float4*)&C[(size_t)row * Nout + col]     = make_float4(o[0], o[1], o[2], o[3]);
        *(float4*)&C[(size_t)row * Nout + col + 4] = make_float4(o[4], o[5], o[6], o[7]);
    }
}

// ---------------- small GEMM (Nout<128): 64x64 tile, 4x4 microtile -----------
__global__ __launch_bounds__(256)
void gemm_kernel(int a_id, const float* __restrict__ W, const float* __restrict__ bias,
                 int c_id, int Nout, int K, int doRelu) {
    const float* A = (const float*)buf_ptr(a_id);
    float* C = buf_ptr(c_id);

    __shared__ float As[16][64];
    __shared__ float Ws[16][64];
    const int tid = threadIdx.x;
    const int tx = tid & 15, ty = tid >> 4;
    const int m0 = blockIdx.y * 64;
    const int n0 = blockIdx.x * 64;
    const int lr = tid >> 2;
    const int lc = (tid & 3) * 4;

    float acc[4][4];
    #pragma unroll
    for (int i = 0; i < 4; i++)
        #pragma unroll
        for (int j = 0; j < 4; j++) acc[i][j] = 0.f;

    for (int kt = 0; kt < K; kt += 16) {
        float4 av = *(const float4*)&A[(size_t)(m0 + lr) * K + kt + lc];
        As[lc + 0][lr] = av.x; As[lc + 1][lr] = av.y;
        As[lc + 2][lr] = av.z; As[lc + 3][lr] = av.w;
        float4 wv = make_float4(0.f, 0.f, 0.f, 0.f);
        if (n0 + lr < Nout)
            wv = *(const float4*)&W[(size_t)(n0 + lr) * K + kt + lc];
        Ws[lc + 0][lr] = wv.x; Ws[lc + 1][lr] = wv.y;
        Ws[lc + 2][lr] = wv.z; Ws[lc + 3][lr] = wv.w;
        __syncthreads();
        #pragma unroll
        for (int k = 0; k < 16; k++) {
            float4 a = *(const float4*)&As[k][ty * 4];
            float4 b = *(const float4*)&Ws[k][tx * 4];
            acc[0][0] = fmaf(a.x, b.x, acc[0][0]); acc[0][1] = fmaf(a.x, b.y, acc[0][1]);
            acc[0][2] = fmaf(a.x, b.z, acc[0][2]); acc[0][3] = fmaf(a.x, b.w, acc[0][3]);
            acc[1][0] = fmaf(a.y, b.x, acc[1][0]); acc[1][1] = fmaf(a.y, b.y, acc[1][1]);
            acc[1][2] = fmaf(a.y, b.z, acc[1][2]); acc[1][3] = fmaf(a.y, b.w, acc[1][3]);
            acc[2][0] = fmaf(a.z, b.x, acc[2][0]); acc[2][1] = fmaf(a.z, b.y, acc[2][1]);
            acc[2][2] = fmaf(a.z, b.z, acc[2][2]); acc[2][3] = fmaf(a.z, b.w, acc[2][3]);
            acc[3][0] = fmaf(a.w, b.x, acc[3][0]); acc[3][1] = fmaf(a.w, b.y, acc[3][1]);
            acc[3][2] = fmaf(a.w, b.z, acc[3][2]); acc[3][3] = fmaf(a.w, b.w, acc[3][3]);
        }
        __syncthreads();
    }

    const int col = n0 + tx * 4;
    if (col < Nout) {
        float bx = bias[col], by = bias[col + 1], bz = bias[col + 2], bw = bias[col + 3];
        #pragma unroll
        for (int i = 0; i < 4; i++) {
            int row = m0 + ty * 4 + i;
            float4 v = make_float4(acc[i][0] + bx, acc[i][1] + by,
                                   acc[i][2] + bz, acc[i][3] + bw);
            if (doRelu) {
                v.x = fmaxf(v.x, 0.f); v.y = fmaxf(v.y, 0.f);
                v.z = fmaxf(v.z, 0.f); v.w = fmaxf(v.w, 0.f);
            }
            *(float4*)&C[(size_t)row * Nout + col] = v;
        }
    }
}

// ---------------- attention scores: warp per (node, head) --------------------
__global__ void attn_scores_kernel(const float* __restrict__ att_src,
                                   const float* __restrict__ att_dst) {
    int gw = (blockIdx.x * blockDim.x + threadIdx.x) >> 5;
    int lane = threadIdx.x & 31;
    if (gw >= N_NODES * HEADS) return;
    int node = gw >> 1, head = gw & 1;
    const float* hp = g_h + (size_t)node * F_DIM + head * OUT_CH + lane * 8;
    const float* sp = att_src + head * OUT_CH + lane * 8;
    const float* dp = att_dst + head * OUT_CH + lane * 8;
    float4 h0 = *(const float4*)hp,  h1 = *(const float4*)(hp + 4);
    float4 s0 = *(const float4*)sp,  s1 = *(const float4*)(sp + 4);
    float4 d0 = *(const float4*)dp,  d1 = *(const float4*)(dp + 4);
    float s = h0.x * s0.x + h0.y * s0.y + h0.z * s0.z + h0.w * s0.w
            + h1.x * s1.x + h1.y * s1.y + h1.z * s1.z + h1.w * s1.w;
    float d = h0.x * d0.x + h0.y * d0.y + h0.z * d0.z + h0.w * d0.w
            + h1.x * d1.x + h1.y * d1.y + h1.z * d1.z + h1.w * d1.w;
    #pragma unroll
    for (int o = 16; o; o >>= 1) {
        s += __shfl_xor_sync(0xffffffffu, s, o);
        d += __shfl_xor_sync(0xffffffffu, d, o);
    }
    if (lane == 0) { g_as[gw] = s; g_ad[gw] = d; }
}

// ---------------- fused GAT: softmax + aggregate + bias + relu ---------------
__global__ __launch_bounds__(128)
void gat_agg_kernel(const float* __restrict__ conv_b) {
    const int dst = blockIdx.x;
    const int t = threadIdx.x;
    __shared__ float red[128];
    __shared__ float sh_a0[128], sh_a1[128];
    __shared__ int   sh_src[128];
    __shared__ float sm0, sm1, ss0, ss1;

    const int off = g_off[dst];
    const int deg = g_off[dst + 1] - off;
    const float ad0 = g_ad[dst * 2], ad1 = g_ad[dst * 2 + 1];
    const float self0 = lrelu(g_as[dst * 2] + ad0);
    const float self1 = lrelu(g_as[dst * 2 + 1] + ad1);

    float m0 = self0, m1 = self1;
    for (int j = t; j < deg; j += 128) {
        int s = g_csr_src[off + j];
        m0 = fmaxf(m0, lrelu(g_as[s * 2] + ad0));
        m1 = fmaxf(m1, lrelu(g_as[s * 2 + 1] + ad1));
    }
    red[t] = m0; __syncthreads();
    for (int d = 64; d; d >>= 1) { if (t < d) red[t] = fmaxf(red[t], red[t + d]); __syncthreads(); }
    if (t == 0) sm0 = red[0];
    __syncthreads();
    red[t] = m1; __syncthreads();
    for (int d = 64; d; d >>= 1) { if (t < d) red[t] = fmaxf(red[t], red[t + d]); __syncthreads(); }
    if (t == 0) sm1 = red[0];
    __syncthreads();
    m0 = sm0; m1 = sm1;

    float s0 = (t == 0) ? expf(self0 - m0) : 0.f;
    float s1 = (t == 0) ? expf(self1 - m1) : 0.f;
    for (int j = t; j < deg; j += 128) {
        int s = g_csr_src[off + j];
        s0 += expf(lrelu(g_as[s * 2] + ad0) - m0);
        s1 += expf(lrelu(g_as[s * 2 + 1] + ad1) - m1);
    }
    red[t] = s0; __syncthreads();
    for (int d = 64; d; d >>= 1) { if (t < d) red[t] += red[t + d]; __syncthreads(); }
    if (t == 0) ss0 = red[0];
    __syncthreads();
    red[t] = s1; __syncthreads();
    for (int d = 64; d; d >>= 1) { if (t < d) red[t] += red[t + d]; __syncthreads(); }
    if (t == 0) ss1 = red[0];
    __syncthreads();
    const float rs0 = 1.f / ss0, rs1 = 1.f / ss1;

    const int head = t >> 6;
    const float mself  = head ? self1 : self0;
    const float mmax   = head ? sm1 : sm0;
    const float rss    = head ? rs1 : rs0;
    const float a_self = expf(mself - mmax) * rss;

    float4 v = *(const float4*)&g_h[(size_t)dst * F_DIM + t * 4];
    float4 acc = make_float4(a_self * v.x, a_self * v.y, a_self * v.z, a_self * v.w);

    for (int c = 0; c < deg; c += 128) {
        int j = c + t;
        if (j < deg) {
            int s = g_csr_src[off + j];
            sh_src[t] = s;
            sh_a0[t] = expf(lrelu(g_as[s * 2] + ad0) - sm0) * rs0;
            sh_a1[t] = expf(lrelu(g_as[s * 2 + 1] + ad1) - sm1) * rs1;
        }
        __syncthreads();
        int cnt = min(128, deg - c);
        for (int j2 = 0; j2 < cnt; j2++) {
            const float4 hv = *(const float4*)&g_h[(size_t)sh_src[j2] * F_DIM + t * 4];
            float a = head ? sh_a1[j2] : sh_a0[j2];
            acc.x = fmaf(a, hv.x, acc.x);
            acc.y = fmaf(a, hv.y, acc.y);
            acc.z = fmaf(a, hv.z, acc.z);
            acc.w = fmaf(a, hv.w, acc.w);
        }
        __syncthreads();
    }

    float4 b = *(const float4*)&conv_b[t * 4];
    acc.x = fmaxf(acc.x + b.x, 0.f);
    acc.y = fmaxf(acc.y + b.y, 0.f);
    acc.z = fmaxf(acc.z + b.z, 0.f);
    acc.w = fmaxf(acc.w + b.w, 0.f);
    *(float4*)&g_gat[(size_t)dst * F_DIM + t * 4] = acc;
}

// ---------------- last MLP layer: 32 -> 3 ------------------------------------
__global__ __launch_bounds__(256)
void final_layer_kernel(const float* __restrict__ W4, const float* __restrict__ b4) {
    __shared__ float w[3][32];
    __shared__ float bb[3];
    int tid = threadIdx.x;
    if (tid < 96) w[tid / 32][tid & 31] = W4[tid];
    if (tid < 3)  bb[tid] = b4[tid];
    __syncthreads();
    int n = blockIdx.x * blockDim.x + tid;
    if (n >= N_NODES) return;
    const float4* hp = (const float4*)(g_h4 + (size_t)n * 32);
    float a0 = bb[0], a1 = bb[1], a2 = bb[2];
    #pragma unroll
    for (int q = 0; q < 8; q++) {
        float4 v = hp[q];
        a0 = fmaf(v.x, w[0][q*4+0], a0); a0 = fmaf(v.y, w[0][q*4+1], a0);
        a0 = fmaf(v.z, w[0][q*4+2], a0); a0 = fmaf(v.w, w[0][q*4+3], a0);
        a1 = fmaf(v.x, w[1][q*4+0], a1); a1 = fmaf(v.y, w[1][q*4+1], a1);
        a1 = fmaf(v.z, w[1][q*4+2], a1); a1 = fmaf(v.w, w[1][q*4+3], a1);
        a2 = fmaf(v.x, w[2][q*4+0], a2); a2 = fmaf(v.y, w[2][q*4+1], a2);
        a2 = fmaf(v.z, w[2][q*4+2], a2); a2 = fmaf(v.w, w[2][q*4+3], a2);
    }
    ((float4*)g_h5)[n] = make_float4(a0, a1, a2, 0.f);
}

// ---------------- pairwise distances ------------------------------------------
__global__ __launch_bounds__(256)
void cdist_kernel(float* __restrict__ out) {
    __shared__ float4 rp[128];
    __shared__ float4 cp[128];
    int tid = threadIdx.x;
    int rb = blockIdx.y * 128, cb = blockIdx.x * 128;
    if (tid < 128) rp[tid] = ((const float4*)g_h5)[rb + tid];
    else           cp[tid - 128] = ((const float4*)g_h5)[cb + tid - 128];
    __syncthreads();
    int tx = tid & 31, ty = tid >> 5;
    float4 q0 = cp[tx * 4 + 0], q1 = cp[tx * 4 + 1],
           q2 = cp[tx * 4 + 2], q3 = cp[tx * 4 + 3];
    #pragma unroll
    for (int j = 0; j < 16; j++) {
        int r = j * 8 + ty;
        float4 p = rp[r];
        float dx, dy, dz, d2;
        float4 o;
        dx = p.x - q0.x; dy = p.y - q0.y; dz = p.z - q0.z;
        d2 = fmaf(dx, dx, fmaf(dy, dy, dz * dz)); o.x = fast_sqrt(d2);
        dx = p.x - q1.x; dy = p.y - q1.y; dz = p.z - q1.z;
        d2 = fmaf(dx, dx, fmaf(dy, dy, dz * dz)); o.y = fast_sqrt(d2);
        dx = p.x - q2.x; dy = p.y - q2.y; dz = p.z - q2.z;
        d2 = fmaf(dx, dx, fmaf(dy, dy, dz * dz)); o.z = fast_sqrt(d2);
        dx = p.x - q3.x; dy = p.y - q3.y; dz = p.z - q3.z;
        d2 = fmaf(dx, dx, fmaf(dy, dy, dz * dz)); o.w = fast_sqrt(d2);
        *(float4*)&out[(size_t)(rb + r) * N_NODES + cb + tx * 4] = o;
    }
}

// ---------------- launch -------------------------------------------------------
extern "C" void kernel_launch(void* const* d_in, const int* in_sizes, int n_in,
                              void* d_out, int out_size) {
    const float* x       = (const float*)d_in[0];
    const void*  ei      = (const void*)d_in[1];
    const float* conv_W  = (const float*)d_in[2];
    const float* att_src = (const float*)d_in[3];
    const float* att_dst = (const float*)d_in[4];
    const float* conv_b  = (const float*)d_in[5];
    const float* Wa = (const float*)d_in[6];  const float* ba = (const float*)d_in[7];
    const float* W1 = (const float*)d_in[8];  const float* b1 = (const float*)d_in[9];
    const float* W2 = (const float*)d_in[10]; const float* b2 = (const float*)d_in[11];
    const float* W3 = (const float*)d_in[12]; const float* b3 = (const float*)d_in[13];
    const float* W4 = (const float*)d_in[14]; const float* b4 = (const float*)d_in[15];
    float*       out = (float*)d_out;

    detect_idx_kernel<<<1, 32>>>(ei);

    // CSR build
    zero_deg_kernel<<<(N_NODES + 255) / 256, 256>>>();
    hist_kernel<<<(E_IN + 255) / 256, 256>>>(ei);
    scan_kernel<<<1, 1024>>>();
    scatter_kernel<<<(E_IN + 255) / 256, 256>>>(ei);

    // h = x @ conv_W^T   [16384,512]
    gemm128_kernel<<<dim3(F_DIM / 128, N_NODES / 128), 256>>>(
        x, -1, conv_W, nullptr, BUF_H, F_DIM, IN_DIM, 0);

    attn_scores_kernel<<<(N_NODES * HEADS * 32 + 255) / 256, 256>>>(att_src, att_dst);

    gat_agg_kernel<<<N_NODES, 128>>>(conv_b);

    // MLP
    gemm128_kernel<<<dim3(256 / 128, N_NODES / 128), 256>>>(nullptr, BUF_GAT, Wa, ba, BUF_H1, 256, 512, 1);
    gemm128_kernel<<<dim3(1,         N_NODES / 128), 256>>>(nullptr, BUF_H1,  W1, b1, BUF_H2, 128, 256, 1);
    gemm_kernel<<<dim3(1, N_NODES / 64), 256>>>(BUF_H2, W2, b2, BUF_H3, 64, 128, 1);
    gemm_kernel<<<dim3(1, N_NODES / 64), 256>>>(BUF_H3, W3, b3, BUF_H4, 32, 64, 1);
    final_layer_kernel<<<N_NODES / 256, 256>>>(W4, b4);

    cdist_kernel<<<dim3(N_NODES / 128, N_NODES / 128), 256>>>(out);
}

// round 7
// speedup vs baseline: 3.1550x; 1.0440x over previous
#include <cuda_runtime.h>
#include <math.h>

#define N_NODES 16384
#define IN_DIM  256
#define HEADS   2
#define OUT_CH  256
#define F_DIM   512
#define E_IN    524288

// ---------------- scratch (device globals) ----------------------------------
__device__ float    g_h   [N_NODES * F_DIM];
__device__ float    g_gat [N_NODES * F_DIM];
__device__ float    g_as  [N_NODES * HEADS];
__device__ float    g_ad  [N_NODES * HEADS];
__device__ int      g_deg [N_NODES];
__device__ int      g_off [N_NODES + 1];
__device__ int      g_csr_src[E_IN];
__device__ float    g_h1  [N_NODES * 256];
__device__ float    g_h2  [N_NODES * 128];
__device__ float    g_h3  [N_NODES * 64];
__device__ float    g_h4  [N_NODES * 32];
__device__ float    g_h5  [N_NODES * 4];
__device__ int      g_is64;

#define BUF_H   0
#define BUF_GAT 1
#define BUF_H1  2
#define BUF_H2  3
#define BUF_H3  4
#define BUF_H4  5
__device__ __forceinline__ float* buf_ptr(int id) {
    switch (id) {
        case BUF_H:   return g_h;
        case BUF_GAT: return g_gat;
        case BUF_H1:  return g_h1;
        case BUF_H2:  return g_h2;
        case BUF_H3:  return g_h3;
        default:      return g_h4;
    }
}

// ---------------- helpers ---------------------------------------------------
__device__ __forceinline__ float lrelu(float v) { return v > 0.f ? v : 0.2f * v; }

__device__ __forceinline__ float fast_sqrt(float d2) {
    float r = __uint_as_float(0x5f3759dfu - (__float_as_uint(d2) >> 1));
    float hd = 0.5f * d2;
    r = r * fmaf(-(hd * r), r, 1.5f);
    r = r * fmaf(-(hd * r), r, 1.5f);
    return d2 * r;
}

// ---------------- edge_index dtype probe -------------------------------------
__global__ void detect_idx_kernel(const void* __restrict__ ei) {
    if (threadIdx.x == 0 && blockIdx.x == 0) {
        const long long* p = (const long long*)ei;
        int ok64 = 1;
        for (int i = 0; i < 256; i++) {
            long long v = p[i];
            if (v < 0 || v >= N_NODES) { ok64 = 0; break; }
        }
        g_is64 = ok64;
    }
}
__device__ __forceinline__ void edge_nodes(const void* __restrict__ ei, int e,
                                           int& src, int& dst) {
    if (g_is64) {
        const long long* p = (const long long*)ei;
        src = (int)p[e]; dst = (int)p[E_IN + e];
    } else {
        const int* p = (const int*)ei;
        src = p[e]; dst = p[E_IN + e];
    }
    src = min(max(src, 0), N_NODES - 1);
    dst = min(max(dst, 0), N_NODES - 1);
}

// ---------------- CSR build ---------------------------------------------------
__global__ void zero_deg_kernel() {
    int i = blockIdx.x * blockDim.x + threadIdx.x;
    if (i < N_NODES) g_deg[i] = 0;
}
__global__ void hist_kernel(const void* __restrict__ ei) {
    int e = blockIdx.x * blockDim.x + threadIdx.x;
    if (e >= E_IN) return;
    int src, dst; edge_nodes(ei, e, src, dst);
    atomicAdd(&g_deg[dst], 1);
}
// shuffle-based single-block scan over 16384 ints (16 per thread, int4 I/O)
__global__ __launch_bounds__(1024)
void scan_kernel() {
    __shared__ int wsum[32];
    int t = threadIdx.x;
    int base = t * 16;
    int4 d0 = *(const int4*)&g_deg[base + 0];
    int4 d1 = *(const int4*)&g_deg[base + 4];
    int4 d2 = *(const int4*)&g_deg[base + 8];
    int4 d3 = *(const int4*)&g_deg[base + 12];
    int v0 = d0.x, v1 = d0.y, v2 = d0.z, v3 = d0.w;
    int v4 = d1.x, v5 = d1.y, v6 = d1.z, v7 = d1.w;
    int v8 = d2.x, v9 = d2.y, v10 = d2.z, v11 = d2.w;
    int v12 = d3.x, v13 = d3.y, v14 = d3.z, v15 = d3.w;
    int l0=0, l1=v0, l2=l1+v1, l3=l2+v2, l4=l3+v3, l5=l4+v4, l6=l5+v5, l7=l6+v6,
        l8=l7+v7, l9=l8+v8, l10=l9+v9, l11=l10+v10, l12=l11+v11, l13=l12+v12,
        l14=l13+v13, l15=l14+v14;
    int s = l15 + v15;
    int lane = t & 31, warp = t >> 5;
    int inc = s;
    #pragma unroll
    for (int d = 1; d < 32; d <<= 1) {
        int v = __shfl_up_sync(0xffffffffu, inc, d);
        if (lane >= d) inc += v;
    }
    if (lane == 31) wsum[warp] = inc;
    __syncthreads();
    if (warp == 0) {
        int v = wsum[lane];
        #pragma unroll
        for (int d = 1; d < 32; d <<= 1) {
            int u = __shfl_up_sync(0xffffffffu, v, d);
            if (lane >= d) v += u;
        }
        wsum[lane] = v;
    }
    __syncthreads();
    int p = (warp ? wsum[warp - 1] : 0) + (inc - s);
    int4 o0 = make_int4(p+l0,  p+l1,  p+l2,  p+l3);
    int4 o1 = make_int4(p+l4,  p+l5,  p+l6,  p+l7);
    int4 o2 = make_int4(p+l8,  p+l9,  p+l10, p+l11);
    int4 o3 = make_int4(p+l12, p+l13, p+l14, p+l15);
    *(int4*)&g_off[base + 0]  = o0;  *(int4*)&g_off[base + 4]  = o1;
    *(int4*)&g_off[base + 8]  = o2;  *(int4*)&g_off[base + 12] = o3;
    *(int4*)&g_deg[base + 0]  = o0;  *(int4*)&g_deg[base + 4]  = o1;
    *(int4*)&g_deg[base + 8]  = o2;  *(int4*)&g_deg[base + 12] = o3;
    if (t == 1023) g_off[N_NODES] = E_IN;
}
__global__ void scatter_kernel(const void* __restrict__ ei) {
    int e = blockIdx.x * blockDim.x + threadIdx.x;
    if (e >= E_IN) return;
    int src, dst; edge_nodes(ei, e, src, dst);
    int pos = atomicAdd(&g_deg[dst], 1);
    g_csr_src[pos] = src;
}

// ---------------- big GEMM: 128x128 tile, 8x8 microtile, double-buffered -----
// requires M%128==0, Nout%128==0, K%16==0
__global__ __launch_bounds__(256)
void gemm128_kernel(const float* __restrict__ a_raw, int a_id,
                    const float* __restrict__ W, const float* __restrict__ bias,
                    int c_id, int Nout, int K, int doRelu) {
    const float* A = a_raw ? a_raw : (const float*)buf_ptr(a_id);
    float* C = buf_ptr(c_id);

    __shared__ __align__(16) float As[2][16][128];
    __shared__ __align__(16) float Ws[2][16][128];
    const int tid = threadIdx.x;
    const int tx = tid & 15, ty = tid >> 4;
    const int m0 = blockIdx.y * 128;
    const int n0 = blockIdx.x * 128;

    // loader mapping: two 16B segments per thread per operand
    const int r0 = (tid * 2 + 0) >> 2, c0 = ((tid * 2 + 0) & 3) * 4;
    const int r1 = (tid * 2 + 1) >> 2, c1 = ((tid * 2 + 1) & 3) * 4;

    float acc[8][8];
    #pragma unroll
    for (int i = 0; i < 8; i++)
        #pragma unroll
        for (int j = 0; j < 8; j++) acc[i][j] = 0.f;

    // load tile 0 directly to smem buffer 0
    {
        float4 va0 = *(const float4*)&A[(size_t)(m0 + r0) * K + c0];
        float4 va1 = *(const float4*)&A[(size_t)(m0 + r1) * K + c1];
        float4 vw0 = *(const float4*)&W[(size_t)(n0 + r0) * K + c0];
        float4 vw1 = *(const float4*)&W[(size_t)(n0 + r1) * K + c1];
        As[0][c0 + 0][r0] = va0.x; As[0][c0 + 1][r0] = va0.y;
        As[0][c0 + 2][r0] = va0.z; As[0][c0 + 3][r0] = va0.w;
        As[0][c1 + 0][r1] = va1.x; As[0][c1 + 1][r1] = va1.y;
        As[0][c1 + 2][r1] = va1.z; As[0][c1 + 3][r1] = va1.w;
        Ws[0][c0 + 0][r0] = vw0.x; Ws[0][c0 + 1][r0] = vw0.y;
        Ws[0][c0 + 2][r0] = vw0.z; Ws[0][c0 + 3][r0] = vw0.w;
        Ws[0][c1 + 0][r1] = vw1.x; Ws[0][c1 + 1][r1] = vw1.y;
        Ws[0][c1 + 2][r1] = vw1.z; Ws[0][c1 + 3][r1] = vw1.w;
    }
    __syncthreads();

    const int T = K >> 4;
    for (int t = 0; t < T; t++) {
        float4 va0, va1, vw0, vw1;
        if (t + 1 < T) {
            int kt = (t + 1) << 4;
            va0 = *(const float4*)&A[(size_t)(m0 + r0) * K + kt + c0];
            va1 = *(const float4*)&A[(size_t)(m0 + r1) * K + kt + c1];
            vw0 = *(const float4*)&W[(size_t)(n0 + r0) * K + kt + c0];
            vw1 = *(const float4*)&W[(size_t)(n0 + r1) * K + kt + c1];
        }
        const int cur = t & 1;
        #pragma unroll
        for (int k = 0; k < 16; k++) {
            float4 a0 = *(const float4*)&As[cur][k][ty * 8];
            float4 a1 = *(const float4*)&As[cur][k][ty * 8 + 4];
            float4 b0 = *(const float4*)&Ws[cur][k][tx * 8];
            float4 b1 = *(const float4*)&Ws[cur][k][tx * 8 + 4];
            float av[8] = {a0.x, a0.y, a0.z, a0.w, a1.x, a1.y, a1.z, a1.w};
            float bv[8] = {b0.x, b0.y, b0.z, b0.w, b1.x, b1.y, b1.z, b1.w};
            #pragma unroll
            for (int i = 0; i < 8; i++)
                #pragma unroll
                for (int j = 0; j < 8; j++)
                    acc[i][j] = fmaf(av[i], bv[j], acc[i][j]);
        }
        if (t + 1 < T) {
            const int nxt = cur ^ 1;
            As[nxt][c0 + 0][r0] = va0.x; As[nxt][c0 + 1][r0] = va0.y;
            As[nxt][c0 + 2][r0] = va0.z; As[nxt][c0 + 3][r0] = va0.w;
            As[nxt][c1 + 0][r1] = va1.x; As[nxt][c1 + 1][r1] = va1.y;
            As[nxt][c1 + 2][r1] = va1.z; As[nxt][c1 + 3][r1] = va1.w;
            Ws[nxt][c0 + 0][r0] = vw0.x; Ws[nxt][c0 + 1][r0] = vw0.y;
            Ws[nxt][c0 + 2][r0] = vw0.z; Ws[nxt][c0 + 3][r0] = vw0.w;
            Ws[nxt][c1 + 0][r1] = vw1.x; Ws[nxt][c1 + 1][r1] = vw1.y;
            Ws[nxt][c1 + 2][r1] = vw1.z; Ws[nxt][c1 + 3][r1] = vw1.w;
        }
        __syncthreads();
    }

    const int col = n0 + tx * 8;
    float bv[8];
    #pragma unroll
    for (int j = 0; j < 8; j++) bv[j] = bias ? bias[col + j] : 0.f;
    #pragma unroll
    for (int i = 0; i < 8; i++) {
        int row = m0 + ty * 8 + i;
        float o[8];
        #pragma unroll
        for (int j = 0; j < 8; j++) {
            o[j] = acc[i][j] + bv[j];
            if (doRelu) o[j] = fmaxf(o[j], 0.f);
        }
        *(float4*)&C[(size_t)row * Nout + col]     = make_float4(o[0], o[1], o[2], o[3]);
        *(float4*)&C[(size_t)row * Nout + col + 4] = make_float4(o[4], o[5], o[6], o[7]);
    }
}

// ---------------- small GEMM (Nout<128): 64x64 tile, 4x4 microtile -----------
__global__ __launch_bounds__(256)
void gemm_kernel(int a_id, const float* __restrict__ W, const float* __restrict__ bias,
                 int c_id, int Nout, int K, int doRelu) {
    const float* A = (const float*)buf_ptr(a_id);
    float* C = buf_ptr(c_id);

    __shared__ float As[16][64];
    __shared__ float Ws[16][64];
    const int tid = threadIdx.x;
    const int tx = tid & 15, ty = tid >> 4;
    const int m0 = blockIdx.y * 64;
    const int n0 = blockIdx.x * 64;
    const int lr = tid >> 2;
    const int lc = (tid & 3) * 4;

    float acc[4][4];
    #pragma unroll
    for (int i = 0; i < 4; i++)
        #pragma unroll
        for (int j = 0; j < 4; j++) acc[i][j] = 0.f;

    for (int kt = 0; kt < K; kt += 16) {
        float4 av = *(const float4*)&A[(size_t)(m0 + lr) * K + kt + lc];
        As[lc + 0][lr] = av.x; As[lc + 1][lr] = av.y;
        As[lc + 2][lr] = av.z; As[lc + 3][lr] = av.w;
        float4 wv = make_float4(0.f, 0.f, 0.f, 0.f);
        if (n0 + lr < Nout)
            wv = *(const float4*)&W[(size_t)(n0 + lr) * K + kt + lc];
        Ws[lc + 0][lr] = wv.x; Ws[lc + 1][lr] = wv.y;
        Ws[lc + 2][lr] = wv.z; Ws[lc + 3][lr] = wv.w;
        __syncthreads();
        #pragma unroll
        for (int k = 0; k < 16; k++) {
            float4 a = *(const float4*)&As[k][ty * 4];
            float4 b = *(const float4*)&Ws[k][tx * 4];
            acc[0][0] = fmaf(a.x, b.x, acc[0][0]); acc[0][1] = fmaf(a.x, b.y, acc[0][1]);
            acc[0][2] = fmaf(a.x, b.z, acc[0][2]); acc[0][3] = fmaf(a.x, b.w, acc[0][3]);
            acc[1][0] = fmaf(a.y, b.x, acc[1][0]); acc[1][1] = fmaf(a.y, b.y, acc[1][1]);
            acc[1][2] = fmaf(a.y, b.z, acc[1][2]); acc[1][3] = fmaf(a.y, b.w, acc[1][3]);
            acc[2][0] = fmaf(a.z, b.x, acc[2][0]); acc[2][1] = fmaf(a.z, b.y, acc[2][1]);
            acc[2][2] = fmaf(a.z, b.z, acc[2][2]); acc[2][3] = fmaf(a.z, b.w, acc[2][3]);
            acc[3][0] = fmaf(a.w, b.x, acc[3][0]); acc[3][1] = fmaf(a.w, b.y, acc[3][1]);
            acc[3][2] = fmaf(a.w, b.z, acc[3][2]); acc[3][3] = fmaf(a.w, b.w, acc[3][3]);
        }
        __syncthreads();
    }

    const int col = n0 + tx * 4;
    if (col < Nout) {
        float bx = bias[col], by = bias[col + 1], bz = bias[col + 2], bw = bias[col + 3];
        #pragma unroll
        for (int i = 0; i < 4; i++) {
            int row = m0 + ty * 4 + i;
            float4 v = make_float4(acc[i][0] + bx, acc[i][1] + by,
                                   acc[i][2] + bz, acc[i][3] + bw);
            if (doRelu) {
                v.x = fmaxf(v.x, 0.f); v.y = fmaxf(v.y, 0.f);
                v.z = fmaxf(v.z, 0.f); v.w = fmaxf(v.w, 0.f);
            }
            *(float4*)&C[(size_t)row * Nout + col] = v;
        }
    }
}

// ---------------- attention scores: warp per (node, head) --------------------
__global__ void attn_scores_kernel(const float* __restrict__ att_src,
                                   const float* __restrict__ att_dst) {
    int gw = (blockIdx.x * blockDim.x + threadIdx.x) >> 5;
    int lane = threadIdx.x & 31;
    if (gw >= N_NODES * HEADS) return;
    int node = gw >> 1, head = gw & 1;
    const float* hp = g_h + (size_t)node * F_DIM + head * OUT_CH + lane * 8;
    const float* sp = att_src + head * OUT_CH + lane * 8;
    const float* dp = att_dst + head * OUT_CH + lane * 8;
    float4 h0 = *(const float4*)hp,  h1 = *(const float4*)(hp + 4);
    float4 s0 = *(const float4*)sp,  s1 = *(const float4*)(sp + 4);
    float4 d0 = *(const float4*)dp,  d1 = *(const float4*)(dp + 4);
    float s = h0.x * s0.x + h0.y * s0.y + h0.z * s0.z + h0.w * s0.w
            + h1.x * s1.x + h1.y * s1.y + h1.z * s1.z + h1.w * s1.w;
    float d = h0.x * d0.x + h0.y * d0.y + h0.z * d0.z + h0.w * d0.w
            + h1.x * d1.x + h1.y * d1.y + h1.z * d1.z + h1.w * d1.w;
    #pragma unroll
    for (int o = 16; o; o >>= 1) {
        s += __shfl_xor_sync(0xffffffffu, s, o);
        d += __shfl_xor_sync(0xffffffffu, d, o);
    }
    if (lane == 0) { g_as[gw] = s; g_ad[gw] = d; }
}

// ---------------- fused GAT: softmax + aggregate + bias + relu ---------------
__global__ __launch_bounds__(128)
void gat_agg_kernel(const float* __restrict__ conv_b) {
    const int dst = blockIdx.x;
    const int t = threadIdx.x;
    __shared__ float red[128];
    __shared__ float sh_a0[128], sh_a1[128];
    __shared__ int   sh_src[128];
    __shared__ float sm0, sm1, ss0, ss1;

    const int off = g_off[dst];
    const int deg = g_off[dst + 1] - off;
    const float ad0 = g_ad[dst * 2], ad1 = g_ad[dst * 2 + 1];
    const float self0 = lrelu(g_as[dst * 2] + ad0);
    const float self1 = lrelu(g_as[dst * 2 + 1] + ad1);

    float m0 = self0, m1 = self1;
    for (int j = t; j < deg; j += 128) {
        int s = g_csr_src[off + j];
        m0 = fmaxf(m0, lrelu(g_as[s * 2] + ad0));
        m1 = fmaxf(m1, lrelu(g_as[s * 2 + 1] + ad1));
    }
    red[t] = m0; __syncthreads();
    for (int d = 64; d; d >>= 1) { if (t < d) red[t] = fmaxf(red[t], red[t + d]); __syncthreads(); }
    if (t == 0) sm0 = red[0];
    __syncthreads();
    red[t] = m1; __syncthreads();
    for (int d = 64; d; d >>= 1) { if (t < d) red[t] = fmaxf(red[t], red[t + d]); __syncthreads(); }
    if (t == 0) sm1 = red[0];
    __syncthreads();
    m0 = sm0; m1 = sm1;

    float s0 = (t == 0) ? expf(self0 - m0) : 0.f;
    float s1 = (t == 0) ? expf(self1 - m1) : 0.f;
    for (int j = t; j < deg; j += 128) {
        int s = g_csr_src[off + j];
        s0 += expf(lrelu(g_as[s * 2] + ad0) - m0);
        s1 += expf(lrelu(g_as[s * 2 + 1] + ad1) - m1);
    }
    red[t] = s0; __syncthreads();
    for (int d = 64; d; d >>= 1) { if (t < d) red[t] += red[t + d]; __syncthreads(); }
    if (t == 0) ss0 = red[0];
    __syncthreads();
    red[t] = s1; __syncthreads();
    for (int d = 64; d; d >>= 1) { if (t < d) red[t] += red[t + d]; __syncthreads(); }
    if (t == 0) ss1 = red[0];
    __syncthreads();
    const float rs0 = 1.f / ss0, rs1 = 1.f / ss1;

    const int head = t >> 6;
    const float mself  = head ? self1 : self0;
    const float mmax   = head ? sm1 : sm0;
    const float rss    = head ? rs1 : rs0;
    const float a_self = expf(mself - mmax) * rss;

    float4 v = *(const float4*)&g_h[(size_t)dst * F_DIM + t * 4];
    float4 acc = make_float4(a_self * v.x, a_self * v.y, a_self * v.z, a_self * v.w);

    for (int c = 0; c < deg; c += 128) {
        int j = c + t;
        if (j < deg) {
            int s = g_csr_src[off + j];
            sh_src[t] = s;
            sh_a0[t] = expf(lrelu(g_as[s * 2] + ad0) - sm0) * rs0;
            sh_a1[t] = expf(lrelu(g_as[s * 2 + 1] + ad1) - sm1) * rs1;
        }
        __syncthreads();
        int cnt = min(128, deg - c);
        for (int j2 = 0; j2 < cnt; j2++) {
            const float4 hv = *(const float4*)&g_h[(size_t)sh_src[j2] * F_DIM + t * 4];
            float a = head ? sh_a1[j2] : sh_a0[j2];
            acc.x = fmaf(a, hv.x, acc.x);
            acc.y = fmaf(a, hv.y, acc.y);
            acc.z = fmaf(a, hv.z, acc.z);
            acc.w = fmaf(a, hv.w, acc.w);
        }
        __syncthreads();
    }

    float4 b = *(const float4*)&conv_b[t * 4];
    acc.x = fmaxf(acc.x + b.x, 0.f);
    acc.y = fmaxf(acc.y + b.y, 0.f);
    acc.z = fmaxf(acc.z + b.z, 0.f);
    acc.w = fmaxf(acc.w + b.w, 0.f);
    *(float4*)&g_gat[(size_t)dst * F_DIM + t * 4] = acc;
}

// ---------------- last MLP layer: 32 -> 3 ------------------------------------
__global__ __launch_bounds__(256)
void final_layer_kernel(const float* __restrict__ W4, const float* __restrict__ b4) {
    __shared__ float w[3][32];
    __shared__ float bb[3];
    int tid = threadIdx.x;
    if (tid < 96) w[tid / 32][tid & 31] = W4[tid];
    if (tid < 3)  bb[tid] = b4[tid];
    __syncthreads();
    int n = blockIdx.x * blockDim.x + tid;
    if (n >= N_NODES) return;
    const float4* hp = (const float4*)(g_h4 + (size_t)n * 32);
    float a0 = bb[0], a1 = bb[1], a2 = bb[2];
    #pragma unroll
    for (int q = 0; q < 8; q++) {
        float4 v = hp[q];
        a0 = fmaf(v.x, w[0][q*4+0], a0); a0 = fmaf(v.y, w[0][q*4+1], a0);
        a0 = fmaf(v.z, w[0][q*4+2], a0); a0 = fmaf(v.w, w[0][q*4+3], a0);
        a1 = fmaf(v.x, w[1][q*4+0], a1); a1 = fmaf(v.y, w[1][q*4+1], a1);
        a1 = fmaf(v.z, w[1][q*4+2], a1); a1 = fmaf(v.w, w[1][q*4+3], a1);
        a2 = fmaf(v.x, w[2][q*4+0], a2); a2 = fmaf(v.y, w[2][q*4+1], a2);
        a2 = fmaf(v.z, w[2][q*4+2], a2); a2 = fmaf(v.w, w[2][q*4+3], a2);
    }
    ((float4*)g_h5)[n] = make_float4(a0, a1, a2, 0.f);
}

// ---------------- pairwise distances ------------------------------------------
__global__ __launch_bounds__(256)
void cdist_kernel(float* __restrict__ out) {
    __shared__ float4 rp[128];
    __shared__ float4 cp[128];
    int tid = threadIdx.x;
    int rb = blockIdx.y * 128, cb = blockIdx.x * 128;
    if (tid < 128) rp[tid] = ((const float4*)g_h5)[rb + tid];
    else           cp[tid - 128] = ((const float4*)g_h5)[cb + tid - 128];
    __syncthreads();
    int tx = tid & 31, ty = tid >> 5;
    float4 q0 = cp[tx * 4 + 0], q1 = cp[tx * 4 + 1],
           q2 = cp[tx * 4 + 2], q3 = cp[tx * 4 + 3];
    #pragma unroll
    for (int j = 0; j < 16; j++) {
        int r = j * 8 + ty;
        float4 p = rp[r];
        float dx, dy, dz, d2;
        float4 o;
        dx = p.x - q0.x; dy = p.y - q0.y; dz = p.z - q0.z;
        d2 = fmaf(dx, dx, fmaf(dy, dy, dz * dz)); o.x = fast_sqrt(d2);
        dx = p.x - q1.x; dy = p.y - q1.y; dz = p.z - q1.z;
        d2 = fmaf(dx, dx, fmaf(dy, dy, dz * dz)); o.y = fast_sqrt(d2);
        dx = p.x - q2.x; dy = p.y - q2.y; dz = p.z - q2.z;
        d2 = fmaf(dx, dx, fmaf(dy, dy, dz * dz)); o.z = fast_sqrt(d2);
        dx = p.x - q3.x; dy = p.y - q3.y; dz = p.z - q3.z;
        d2 = fmaf(dx, dx, fmaf(dy, dy, dz * dz)); o.w = fast_sqrt(d2);
        *(float4*)&out[(size_t)(rb + r) * N_NODES + cb + tx * 4] = o;
    }
}

// ---------------- launch -------------------------------------------------------
extern "C" void kernel_launch(void* const* d_in, const int* in_sizes, int n_in,
                              void* d_out, int out_size) {
    const float* x       = (const float*)d_in[0];
    const void*  ei      = (const void*)d_in[1];
    const float* conv_W  = (const float*)d_in[2];
    const float* att_src = (const float*)d_in[3];
    const float* att_dst = (const float*)d_in[4];
    const float* conv_b  = (const float*)d_in[5];
    const float* Wa = (const float*)d_in[6];  const float* ba = (const float*)d_in[7];
    const float* W1 = (const float*)d_in[8];  const float* b1 = (const float*)d_in[9];
    const float* W2 = (const float*)d_in[10]; const float* b2 = (const float*)d_in[11];
    const float* W3 = (const float*)d_in[12]; const float* b3 = (const float*)d_in[13];
    const float* W4 = (const float*)d_in[14]; const float* b4 = (const float*)d_in[15];
    float*       out = (float*)d_out;

    // launch order arranged so the conv GEMM is the 4th launch (ncu captures #4)
    detect_idx_kernel<<<1, 32>>>(ei);                              // 1
    zero_deg_kernel<<<(N_NODES + 255) / 256, 256>>>();             // 2
    hist_kernel<<<(E_IN + 255) / 256, 256>>>(ei);                  // 3

    // h = x @ conv_W^T   [16384,512]
    gemm128_kernel<<<dim3(F_DIM / 128, N_NODES / 128), 256>>>(     // 4 (profiled)
        x, -1, conv_W, nullptr, BUF_H, F_DIM, IN_DIM, 0);

    scan_kernel<<<1, 1024>>>();                                    // 5
    scatter_kernel<<<(E_IN + 255) / 256, 256>>>(ei);               // 6

    attn_scores_kernel<<<(N_NODES * HEADS * 32 + 255) / 256, 256>>>(att_src, att_dst);

    gat_agg_kernel<<<N_NODES, 128>>>(conv_b);

    // MLP
    gemm128_kernel<<<dim3(256 / 128, N_NODES / 128), 256>>>(nullptr, BUF_GAT, Wa, ba, BUF_H1, 256, 512, 1);
    gemm128_kernel<<<dim3(1,         N_NODES / 128), 256>>>(nullptr, BUF_H1,  W1, b1, BUF_H2, 128, 256, 1);
    gemm_kernel<<<dim3(1, N_NODES / 64), 256>>>(BUF_H2, W2, b2, BUF_H3, 64, 128, 1);
    gemm_kernel<<<dim3(1, N_NODES / 64), 256>>>(BUF_H3, W3, b3, BUF_H4, 32, 64, 1);
    final_layer_kernel<<<N_NODES / 256, 256>>>(W4, b4);

    cdist_kernel<<<dim3(N_NODES / 128, N_NODES / 128), 256>>>(out);
}

// round 8
// speedup vs baseline: 3.8723x; 1.2274x over previous
#include <cuda_runtime.h>
#include <cuda_bf16.h>
#include <math.h>

#define N_NODES 16384
#define IN_DIM  256
#define HEADS   2
#define OUT_CH  256
#define F_DIM   512
#define E_IN    524288

// ---------------- scratch (device globals) ----------------------------------
__device__ float    g_h   [N_NODES * F_DIM];
__device__ float    g_gat [N_NODES * F_DIM];
__device__ float    g_as  [N_NODES * HEADS];
__device__ float    g_ad  [N_NODES * HEADS];
__device__ int      g_deg [N_NODES];
__device__ int      g_off [N_NODES + 1];
__device__ int      g_csr_src[E_IN];
__device__ float    g_h1  [N_NODES * 256];
__device__ float    g_h2  [N_NODES * 128];
__device__ float    g_h3  [N_NODES * 64];
__device__ float    g_h4  [N_NODES * 32];
__device__ float    g_h5  [N_NODES * 4];
__device__ int      g_is64;
// bf16 split scratch
__device__ __nv_bfloat16 g_ah[N_NODES * F_DIM];
__device__ __nv_bfloat16 g_al[N_NODES * F_DIM];
__device__ __nv_bfloat16 g_wh[512 * 256 > 256 * 512 ? 512 * 256 : 256 * 512];
__device__ __nv_bfloat16 g_wl[512 * 256 > 256 * 512 ? 512 * 256 : 256 * 512];

#define BUF_H   0
#define BUF_GAT 1
#define BUF_H1  2
#define BUF_H2  3
#define BUF_H3  4
#define BUF_H4  5
__device__ __forceinline__ float* buf_ptr(int id) {
    switch (id) {
        case BUF_H:   return g_h;
        case BUF_GAT: return g_gat;
        case BUF_H1:  return g_h1;
        case BUF_H2:  return g_h2;
        case BUF_H3:  return g_h3;
        default:      return g_h4;
    }
}

// ---------------- helpers ---------------------------------------------------
__device__ __forceinline__ float lrelu(float v) { return v > 0.f ? v : 0.2f * v; }

__device__ __forceinline__ float fast_sqrt(float d2) {
    float r = __uint_as_float(0x5f3759dfu - (__float_as_uint(d2) >> 1));
    float hd = 0.5f * d2;
    r = r * fmaf(-(hd * r), r, 1.5f);
    r = r * fmaf(-(hd * r), r, 1.5f);
    return d2 * r;
}

__device__ __forceinline__ void mma_bf16(float* c, const unsigned* a, const unsigned* b) {
    asm volatile(
        "mma.sync.aligned.m16n8k16.row.col.f32.bf16.bf16.f32 "
        "{%0,%1,%2,%3}, {%4,%5,%6,%7}, {%8,%9}, {%0,%1,%2,%3};"
        : "+f"(c[0]), "+f"(c[1]), "+f"(c[2]), "+f"(c[3])
        : "r"(a[0]), "r"(a[1]), "r"(a[2]), "r"(a[3]), "r"(b[0]), "r"(b[1]));
}

// ---------------- split fp32 -> bf16 hi/lo ------------------------------------
// dest: 0 = activation scratch (g_ah/g_al), 1 = weight scratch (g_wh/g_wl)
__global__ void split_kernel(const float* __restrict__ raw, int a_id, int n4, int dest) {
    int i = blockIdx.x * blockDim.x + threadIdx.x;
    if (i >= n4) return;
    const float* A = raw ? raw : (const float*)buf_ptr(a_id);
    float4 v = ((const float4*)A)[i];
    __nv_bfloat16 hx = __float2bfloat16_rn(v.x);
    __nv_bfloat16 hy = __float2bfloat16_rn(v.y);
    __nv_bfloat16 hz = __float2bfloat16_rn(v.z);
    __nv_bfloat16 hw = __float2bfloat16_rn(v.w);
    __nv_bfloat16 lx = __float2bfloat16_rn(v.x - __bfloat162float(hx));
    __nv_bfloat16 ly = __float2bfloat16_rn(v.y - __bfloat162float(hy));
    __nv_bfloat16 lz = __float2bfloat16_rn(v.z - __bfloat162float(hz));
    __nv_bfloat16 lw = __float2bfloat16_rn(v.w - __bfloat162float(hw));
    __nv_bfloat162 h0; h0.x = hx; h0.y = hy;
    __nv_bfloat162 h1; h1.x = hz; h1.y = hw;
    __nv_bfloat162 l0; l0.x = lx; l0.y = ly;
    __nv_bfloat162 l1; l1.x = lz; l1.y = lw;
    __nv_bfloat162* dh = dest ? (__nv_bfloat162*)g_wh : (__nv_bfloat162*)g_ah;
    __nv_bfloat162* dl = dest ? (__nv_bfloat162*)g_wl : (__nv_bfloat162*)g_al;
    dh[i * 2]     = h0; dh[i * 2 + 1] = h1;
    dl[i * 2]     = l0; dl[i * 2 + 1] = l1;
}

// ---------------- tensor-core GEMM: C = act(A @ W^T + b), split-bf16 ----------
// A from g_ah/g_al [M,K], W from g_wh/g_wl [Nout,K]. M%128==0, Nout%128==0, K%16==0.
#define SP 24   // smem row stride in bf16 (conflict-free frag loads)
__global__ __launch_bounds__(256, 1)
void gemm_tc_kernel(const float* __restrict__ bias, int c_id,
                    int Nout, int K, int doRelu) {
    float* C = buf_ptr(c_id);
    __shared__ __align__(16) __nv_bfloat16 sAh[2][128 * SP];
    __shared__ __align__(16) __nv_bfloat16 sAl[2][128 * SP];
    __shared__ __align__(16) __nv_bfloat16 sBh[2][128 * SP];
    __shared__ __align__(16) __nv_bfloat16 sBl[2][128 * SP];

    const int tid  = threadIdx.x;
    const int m0 = blockIdx.y * 128, n0 = blockIdx.x * 128;
    const int lrow = tid >> 1, lhalf = tid & 1;
    const size_t gA = (size_t)(m0 + lrow) * K + lhalf * 8;
    const size_t gB = (size_t)(n0 + lrow) * K + lhalf * 8;
    const int sofs = lrow * SP + lhalf * 8;

    const int w = tid >> 5, lane = tid & 31;
    const int wm = (w & 1) * 64, wn = (w >> 1) * 32;
    const int gr = lane >> 2, tg = lane & 3;

    float acc[4][4][4];
    #pragma unroll
    for (int mt = 0; mt < 4; mt++)
        #pragma unroll
        for (int nt = 0; nt < 4; nt++)
            #pragma unroll
            for (int r = 0; r < 4; r++) acc[mt][nt][r] = 0.f;

    // preload stage 0
    *(uint4*)&sAh[0][sofs] = *(const uint4*)&g_ah[gA];
    *(uint4*)&sAl[0][sofs] = *(const uint4*)&g_al[gA];
    *(uint4*)&sBh[0][sofs] = *(const uint4*)&g_wh[gB];
    *(uint4*)&sBl[0][sofs] = *(const uint4*)&g_wl[gB];
    __syncthreads();

    const int T = K >> 4;
    for (int t = 0; t < T; t++) {
        uint4 pah, pal, pbh, pbl;
        if (t + 1 < T) {
            int kt = (t + 1) << 4;
            pah = *(const uint4*)&g_ah[gA + kt];
            pal = *(const uint4*)&g_al[gA + kt];
            pbh = *(const uint4*)&g_wh[gB + kt];
            pbl = *(const uint4*)&g_wl[gB + kt];
        }
        const int cur = t & 1;

        unsigned ah[4][4], al[4][4], bh[4][2], bl[4][2];
        #pragma unroll
        for (int mt = 0; mt < 4; mt++) {
            int r = wm + mt * 16 + gr;
            ah[mt][0] = *(const unsigned*)&sAh[cur][r * SP + 2 * tg];
            ah[mt][1] = *(const unsigned*)&sAh[cur][(r + 8) * SP + 2 * tg];
            ah[mt][2] = *(const unsigned*)&sAh[cur][r * SP + 8 + 2 * tg];
            ah[mt][3] = *(const unsigned*)&sAh[cur][(r + 8) * SP + 8 + 2 * tg];
            al[mt][0] = *(const unsigned*)&sAl[cur][r * SP + 2 * tg];
            al[mt][1] = *(const unsigned*)&sAl[cur][(r + 8) * SP + 2 * tg];
            al[mt][2] = *(const unsigned*)&sAl[cur][r * SP + 8 + 2 * tg];
            al[mt][3] = *(const unsigned*)&sAl[cur][(r + 8) * SP + 8 + 2 * tg];
        }
        #pragma unroll
        for (int nt = 0; nt < 4; nt++) {
            int cn = wn + nt * 8 + gr;
            bh[nt][0] = *(const unsigned*)&sBh[cur][cn * SP + 2 * tg];
            bh[nt][1] = *(const unsigned*)&sBh[cur][cn * SP + 8 + 2 * tg];
            bl[nt][0] = *(const unsigned*)&sBl[cur][cn * SP + 2 * tg];
            bl[nt][1] = *(const unsigned*)&sBl[cur][cn * SP + 8 + 2 * tg];
        }
        #pragma unroll
        for (int mt = 0; mt < 4; mt++)
            #pragma unroll
            for (int nt = 0; nt < 4; nt++) {
                mma_bf16(acc[mt][nt], ah[mt], bh[nt]);
                mma_bf16(acc[mt][nt], ah[mt], bl[nt]);
                mma_bf16(acc[mt][nt], al[mt], bh[nt]);
            }

        if (t + 1 < T) {
            const int nxt = cur ^ 1;
            *(uint4*)&sAh[nxt][sofs] = pah;
            *(uint4*)&sAl[nxt][sofs] = pal;
            *(uint4*)&sBh[nxt][sofs] = pbh;
            *(uint4*)&sBl[nxt][sofs] = pbl;
        }
        __syncthreads();
    }

    // epilogue
    #pragma unroll
    for (int mt = 0; mt < 4; mt++) {
        int row = m0 + wm + mt * 16 + gr;
        #pragma unroll
        for (int nt = 0; nt < 4; nt++) {
            int col = n0 + wn + nt * 8 + 2 * tg;
            float b0 = bias ? bias[col] : 0.f;
            float b1 = bias ? bias[col + 1] : 0.f;
            float o0 = acc[mt][nt][0] + b0, o1 = acc[mt][nt][1] + b1;
            float o2 = acc[mt][nt][2] + b0, o3 = acc[mt][nt][3] + b1;
            if (doRelu) {
                o0 = fmaxf(o0, 0.f); o1 = fmaxf(o1, 0.f);
                o2 = fmaxf(o2, 0.f); o3 = fmaxf(o3, 0.f);
            }
            *(float2*)&C[(size_t)row * Nout + col]       = make_float2(o0, o1);
            *(float2*)&C[(size_t)(row + 8) * Nout + col] = make_float2(o2, o3);
        }
    }
}

// ---------------- edge_index dtype probe -------------------------------------
__global__ void detect_idx_kernel(const void* __restrict__ ei) {
    if (threadIdx.x == 0 && blockIdx.x == 0) {
        const long long* p = (const long long*)ei;
        int ok64 = 1;
        for (int i = 0; i < 256; i++) {
            long long v = p[i];
            if (v < 0 || v >= N_NODES) { ok64 = 0; break; }
        }
        g_is64 = ok64;
    }
}
__device__ __forceinline__ void edge_nodes(const void* __restrict__ ei, int e,
                                           int& src, int& dst) {
    if (g_is64) {
        const long long* p = (const long long*)ei;
        src = (int)p[e]; dst = (int)p[E_IN + e];
    } else {
        const int* p = (const int*)ei;
        src = p[e]; dst = p[E_IN + e];
    }
    src = min(max(src, 0), N_NODES - 1);
    dst = min(max(dst, 0), N_NODES - 1);
}

// ---------------- CSR build ---------------------------------------------------
__global__ void zero_deg_kernel() {
    int i = blockIdx.x * blockDim.x + threadIdx.x;
    if (i < N_NODES) g_deg[i] = 0;
}
__global__ void hist_kernel(const void* __restrict__ ei) {
    int e = blockIdx.x * blockDim.x + threadIdx.x;
    if (e >= E_IN) return;
    int src, dst; edge_nodes(ei, e, src, dst);
    atomicAdd(&g_deg[dst], 1);
}
__global__ __launch_bounds__(1024)
void scan_kernel() {
    __shared__ int wsum[32];
    int t = threadIdx.x;
    int base = t * 16;
    int4 d0 = *(const int4*)&g_deg[base + 0];
    int4 d1 = *(const int4*)&g_deg[base + 4];
    int4 d2 = *(const int4*)&g_deg[base + 8];
    int4 d3 = *(const int4*)&g_deg[base + 12];
    int v0 = d0.x, v1 = d0.y, v2 = d0.z, v3 = d0.w;
    int v4 = d1.x, v5 = d1.y, v6 = d1.z, v7 = d1.w;
    int v8 = d2.x, v9 = d2.y, v10 = d2.z, v11 = d2.w;
    int v12 = d3.x, v13 = d3.y, v14 = d3.z, v15 = d3.w;
    int l0=0, l1=v0, l2=l1+v1, l3=l2+v2, l4=l3+v3, l5=l4+v4, l6=l5+v5, l7=l6+v6,
        l8=l7+v7, l9=l8+v8, l10=l9+v9, l11=l10+v10, l12=l11+v11, l13=l12+v12,
        l14=l13+v13, l15=l14+v14;
    int s = l15 + v15;
    int lane = t & 31, warp = t >> 5;
    int inc = s;
    #pragma unroll
    for (int d = 1; d < 32; d <<= 1) {
        int v = __shfl_up_sync(0xffffffffu, inc, d);
        if (lane >= d) inc += v;
    }
    if (lane == 31) wsum[warp] = inc;
    __syncthreads();
    if (warp == 0) {
        int v = wsum[lane];
        #pragma unroll
        for (int d = 1; d < 32; d <<= 1) {
            int u = __shfl_up_sync(0xffffffffu, v, d);
            if (lane >= d) v += u;
        }
        wsum[lane] = v;
    }
    __syncthreads();
    int p = (warp ? wsum[warp - 1] : 0) + (inc - s);
    int4 o0 = make_int4(p+l0,  p+l1,  p+l2,  p+l3);
    int4 o1 = make_int4(p+l4,  p+l5,  p+l6,  p+l7);
    int4 o2 = make_int4(p+l8,  p+l9,  p+l10, p+l11);
    int4 o3 = make_int4(p+l12, p+l13, p+l14, p+l15);
    *(int4*)&g_off[base + 0]  = o0;  *(int4*)&g_off[base + 4]  = o1;
    *(int4*)&g_off[base + 8]  = o2;  *(int4*)&g_off[base + 12] = o3;
    *(int4*)&g_deg[base + 0]  = o0;  *(int4*)&g_deg[base + 4]  = o1;
    *(int4*)&g_deg[base + 8]  = o2;  *(int4*)&g_deg[base + 12] = o3;
    if (t == 1023) g_off[N_NODES] = E_IN;
}
__global__ void scatter_kernel(const void* __restrict__ ei) {
    int e = blockIdx.x * blockDim.x + threadIdx.x;
    if (e >= E_IN) return;
    int src, dst; edge_nodes(ei, e, src, dst);
    int pos = atomicAdd(&g_deg[dst], 1);
    g_csr_src[pos] = src;
}

// ---------------- small GEMM (Nout<128): 64x64 tile, 4x4 microtile -----------
__global__ __launch_bounds__(256)
void gemm_kernel(int a_id, const float* __restrict__ W, const float* __restrict__ bias,
                 int c_id, int Nout, int K, int doRelu) {
    const float* A = (const float*)buf_ptr(a_id);
    float* C = buf_ptr(c_id);

    __shared__ float As[16][64];
    __shared__ float Ws[16][64];
    const int tid = threadIdx.x;
    const int tx = tid & 15, ty = tid >> 4;
    const int m0 = blockIdx.y * 64;
    const int n0 = blockIdx.x * 64;
    const int lr = tid >> 2;
    const int lc = (tid & 3) * 4;

    float acc[4][4];
    #pragma unroll
    for (int i = 0; i < 4; i++)
        #pragma unroll
        for (int j = 0; j < 4; j++) acc[i][j] = 0.f;

    for (int kt = 0; kt < K; kt += 16) {
        float4 av = *(const float4*)&A[(size_t)(m0 + lr) * K + kt + lc];
        As[lc + 0][lr] = av.x; As[lc + 1][lr] = av.y;
        As[lc + 2][lr] = av.z; As[lc + 3][lr] = av.w;
        float4 wv = make_float4(0.f, 0.f, 0.f, 0.f);
        if (n0 + lr < Nout)
            wv = *(const float4*)&W[(size_t)(n0 + lr) * K + kt + lc];
        Ws[lc + 0][lr] = wv.x; Ws[lc + 1][lr] = wv.y;
        Ws[lc + 2][lr] = wv.z; Ws[lc + 3][lr] = wv.w;
        __syncthreads();
        #pragma unroll
        for (int k = 0; k < 16; k++) {
            float4 a = *(const float4*)&As[k][ty * 4];
            float4 b = *(const float4*)&Ws[k][tx * 4];
            acc[0][0] = fmaf(a.x, b.x, acc[0][0]); acc[0][1] = fmaf(a.x, b.y, acc[0][1]);
            acc[0][2] = fmaf(a.x, b.z, acc[0][2]); acc[0][3] = fmaf(a.x, b.w, acc[0][3]);
            acc[1][0] = fmaf(a.y, b.x, acc[1][0]); acc[1][1] = fmaf(a.y, b.y, acc[1][1]);
            acc[1][2] = fmaf(a.y, b.z, acc[1][2]); acc[1][3] = fmaf(a.y, b.w, acc[1][3]);
            acc[2][0] = fmaf(a.z, b.x, acc[2][0]); acc[2][1] = fmaf(a.z, b.y, acc[2][1]);
            acc[2][2] = fmaf(a.z, b.z, acc[2][2]); acc[2][3] = fmaf(a.z, b.w, acc[2][3]);
            acc[3][0] = fmaf(a.w, b.x, acc[3][0]); acc[3][1] = fmaf(a.w, b.y, acc[3][1]);
            acc[3][2] = fmaf(a.w, b.z, acc[3][2]); acc[3][3] = fmaf(a.w, b.w, acc[3][3]);
        }
        __syncthreads();
    }

    const int col = n0 + tx * 4;
    if (col < Nout) {
        float bx = bias[col], by = bias[col + 1], bz = bias[col + 2], bw = bias[col + 3];
        #pragma unroll
        for (int i = 0; i < 4; i++) {
            int row = m0 + ty * 4 + i;
            float4 v = make_float4(acc[i][0] + bx, acc[i][1] + by,
                                   acc[i][2] + bz, acc[i][3] + bw);
            if (doRelu) {
                v.x = fmaxf(v.x, 0.f); v.y = fmaxf(v.y, 0.f);
                v.z = fmaxf(v.z, 0.f); v.w = fmaxf(v.w, 0.f);
            }
            *(float4*)&C[(size_t)row * Nout + col] = v;
        }
    }
}

// ---------------- attention scores: warp per (node, head) --------------------
__global__ void attn_scores_kernel(const float* __restrict__ att_src,
                                   const float* __restrict__ att_dst) {
    int gw = (blockIdx.x * blockDim.x + threadIdx.x) >> 5;
    int lane = threadIdx.x & 31;
    if (gw >= N_NODES * HEADS) return;
    int node = gw >> 1, head = gw & 1;
    const float* hp = g_h + (size_t)node * F_DIM + head * OUT_CH + lane * 8;
    const float* sp = att_src + head * OUT_CH + lane * 8;
    const float* dp = att_dst + head * OUT_CH + lane * 8;
    float4 h0 = *(const float4*)hp,  h1 = *(const float4*)(hp + 4);
    float4 s0 = *(const float4*)sp,  s1 = *(const float4*)(sp + 4);
    float4 d0 = *(const float4*)dp,  d1 = *(const float4*)(dp + 4);
    float s = h0.x * s0.x + h0.y * s0.y + h0.z * s0.z + h0.w * s0.w
            + h1.x * s1.x + h1.y * s1.y + h1.z * s1.z + h1.w * s1.w;
    float d = h0.x * d0.x + h0.y * d0.y + h0.z * d0.z + h0.w * d0.w
            + h1.x * d1.x + h1.y * d1.y + h1.z * d1.z + h1.w * d1.w;
    #pragma unroll
    for (int o = 16; o; o >>= 1) {
        s += __shfl_xor_sync(0xffffffffu, s, o);
        d += __shfl_xor_sync(0xffffffffu, d, o);
    }
    if (lane == 0) { g_as[gw] = s; g_ad[gw] = d; }
}

// ---------------- fused GAT: softmax + aggregate + bias + relu ---------------
__global__ __launch_bounds__(128)
void gat_agg_kernel(const float* __restrict__ conv_b) {
    const int dst = blockIdx.x;
    const int t = threadIdx.x;
    __shared__ float red[128];
    __shared__ float sh_a0[128], sh_a1[128];
    __shared__ int   sh_src[128];
    __shared__ float sm0, sm1, ss0, ss1;

    const int off = g_off[dst];
    const int deg = g_off[dst + 1] - off;
    const float ad0 = g_ad[dst * 2], ad1 = g_ad[dst * 2 + 1];
    const float self0 = lrelu(g_as[dst * 2] + ad0);
    const float self1 = lrelu(g_as[dst * 2 + 1] + ad1);

    float m0 = self0, m1 = self1;
    for (int j = t; j < deg; j += 128) {
        int s = g_csr_src[off + j];
        m0 = fmaxf(m0, lrelu(g_as[s * 2] + ad0));
        m1 = fmaxf(m1, lrelu(g_as[s * 2 + 1] + ad1));
    }
    red[t] = m0; __syncthreads();
    for (int d = 64; d; d >>= 1) { if (t < d) red[t] = fmaxf(red[t], red[t + d]); __syncthreads(); }
    if (t == 0) sm0 = red[0];
    __syncthreads();
    red[t] = m1; __syncthreads();
    for (int d = 64; d; d >>= 1) { if (t < d) red[t] = fmaxf(red[t], red[t + d]); __syncthreads(); }
    if (t == 0) sm1 = red[0];
    __syncthreads();
    m0 = sm0; m1 = sm1;

    float s0 = (t == 0) ? expf(self0 - m0) : 0.f;
    float s1 = (t == 0) ? expf(self1 - m1) : 0.f;
    for (int j = t; j < deg; j += 128) {
        int s = g_csr_src[off + j];
        s0 += expf(lrelu(g_as[s * 2] + ad0) - m0);
        s1 += expf(lrelu(g_as[s * 2 + 1] + ad1) - m1);
    }
    red[t] = s0; __syncthreads();
    for (int d = 64; d; d >>= 1) { if (t < d) red[t] += red[t + d]; __syncthreads(); }
    if (t == 0) ss0 = red[0];
    __syncthreads();
    red[t] = s1; __syncthreads();
    for (int d = 64; d; d >>= 1) { if (t < d) red[t] += red[t + d]; __syncthreads(); }
    if (t == 0) ss1 = red[0];
    __syncthreads();
    const float rs0 = 1.f / ss0, rs1 = 1.f / ss1;

    const int head = t >> 6;
    const float mself  = head ? self1 : self0;
    const float mmax   = head ? sm1 : sm0;
    const float rss    = head ? rs1 : rs0;
    const float a_self = expf(mself - mmax) * rss;

    float4 v = *(const float4*)&g_h[(size_t)dst * F_DIM + t * 4];
    float4 acc = make_float4(a_self * v.x, a_self * v.y, a_self * v.z, a_self * v.w);

    for (int c = 0; c < deg; c += 128) {
        int j = c + t;
        if (j < deg) {
            int s = g_csr_src[off + j];
            sh_src[t] = s;
            sh_a0[t] = expf(lrelu(g_as[s * 2] + ad0) - sm0) * rs0;
            sh_a1[t] = expf(lrelu(g_as[s * 2 + 1] + ad1) - sm1) * rs1;
        }
        __syncthreads();
        int cnt = min(128, deg - c);
        for (int j2 = 0; j2 < cnt; j2++) {
            const float4 hv = *(const float4*)&g_h[(size_t)sh_src[j2] * F_DIM + t * 4];
            float a = head ? sh_a1[j2] : sh_a0[j2];
            acc.x = fmaf(a, hv.x, acc.x);
            acc.y = fmaf(a, hv.y, acc.y);
            acc.z = fmaf(a, hv.z, acc.z);
            acc.w = fmaf(a, hv.w, acc.w);
        }
        __syncthreads();
    }

    float4 b = *(const float4*)&conv_b[t * 4];
    acc.x = fmaxf(acc.x + b.x, 0.f);
    acc.y = fmaxf(acc.y + b.y, 0.f);
    acc.z = fmaxf(acc.z + b.z, 0.f);
    acc.w = fmaxf(acc.w + b.w, 0.f);
    *(float4*)&g_gat[(size_t)dst * F_DIM + t * 4] = acc;
}

// ---------------- last MLP layer: 32 -> 3 ------------------------------------
__global__ __launch_bounds__(256)
void final_layer_kernel(const float* __restrict__ W4, const float* __restrict__ b4) {
    __shared__ float w[3][32];
    __shared__ float bb[3];
    int tid = threadIdx.x;
    if (tid < 96) w[tid / 32][tid & 31] = W4[tid];
    if (tid < 3)  bb[tid] = b4[tid];
    __syncthreads();
    int n = blockIdx.x * blockDim.x + tid;
    if (n >= N_NODES) return;
    const float4* hp = (const float4*)(g_h4 + (size_t)n * 32);
    float a0 = bb[0], a1 = bb[1], a2 = bb[2];
    #pragma unroll
    for (int q = 0; q < 8; q++) {
        float4 v = hp[q];
        a0 = fmaf(v.x, w[0][q*4+0], a0); a0 = fmaf(v.y, w[0][q*4+1], a0);
        a0 = fmaf(v.z, w[0][q*4+2], a0); a0 = fmaf(v.w, w[0][q*4+3], a0);
        a1 = fmaf(v.x, w[1][q*4+0], a1); a1 = fmaf(v.y, w[1][q*4+1], a1);
        a1 = fmaf(v.z, w[1][q*4+2], a1); a1 = fmaf(v.w, w[1][q*4+3], a1);
        a2 = fmaf(v.x, w[2][q*4+0], a2); a2 = fmaf(v.y, w[2][q*4+1], a2);
        a2 = fmaf(v.z, w[2][q*4+2], a2); a2 = fmaf(v.w, w[2][q*4+3], a2);
    }
    ((float4*)g_h5)[n] = make_float4(a0, a1, a2, 0.f);
}

// ---------------- pairwise distances ------------------------------------------
__global__ __launch_bounds__(256)
void cdist_kernel(float* __restrict__ out) {
    __shared__ float4 rp[128];
    __shared__ float4 cp[128];
    int tid = threadIdx.x;
    int rb = blockIdx.y * 128, cb = blockIdx.x * 128;
    if (tid < 128) rp[tid] = ((const float4*)g_h5)[rb + tid];
    else           cp[tid - 128] = ((const float4*)g_h5)[cb + tid - 128];
    __syncthreads();
    int tx = tid & 31, ty = tid >> 5;
    float4 q0 = cp[tx * 4 + 0], q1 = cp[tx * 4 + 1],
           q2 = cp[tx * 4 + 2], q3 = cp[tx * 4 + 3];
    #pragma unroll
    for (int j = 0; j < 16; j++) {
        int r = j * 8 + ty;
        float4 p = rp[r];
        float dx, dy, dz, d2;
        float4 o;
        dx = p.x - q0.x; dy = p.y - q0.y; dz = p.z - q0.z;
        d2 = fmaf(dx, dx, fmaf(dy, dy, dz * dz)); o.x = fast_sqrt(d2);
        dx = p.x - q1.x; dy = p.y - q1.y; dz = p.z - q1.z;
        d2 = fmaf(dx, dx, fmaf(dy, dy, dz * dz)); o.y = fast_sqrt(d2);
        dx = p.x - q2.x; dy = p.y - q2.y; dz = p.z - q2.z;
        d2 = fmaf(dx, dx, fmaf(dy, dy, dz * dz)); o.z = fast_sqrt(d2);
        dx = p.x - q3.x; dy = p.y - q3.y; dz = p.z - q3.z;
        d2 = fmaf(dx, dx, fmaf(dy, dy, dz * dz)); o.w = fast_sqrt(d2);
        __stcs((float4*)&out[(size_t)(rb + r) * N_NODES + cb + tx * 4], o);
    }
}

// ---------------- launch -------------------------------------------------------
extern "C" void kernel_launch(void* const* d_in, const int* in_sizes, int n_in,
                              void* d_out, int out_size) {
    const float* x       = (const float*)d_in[0];
    const void*  ei      = (const void*)d_in[1];
    const float* conv_W  = (const float*)d_in[2];
    const float* att_src = (const float*)d_in[3];
    const float* att_dst = (const float*)d_in[4];
    const float* conv_b  = (const float*)d_in[5];
    const float* Wa = (const float*)d_in[6];  const float* ba = (const float*)d_in[7];
    const float* W1 = (const float*)d_in[8];  const float* b1 = (const float*)d_in[9];
    const float* W2 = (const float*)d_in[10]; const float* b2 = (const float*)d_in[11];
    const float* W3 = (const float*)d_in[12]; const float* b3 = (const float*)d_in[13];
    const float* W4 = (const float*)d_in[14]; const float* b4 = (const float*)d_in[15];
    float*       out = (float*)d_out;

    detect_idx_kernel<<<1, 32>>>(ei);                                        // 1

    // conv GEMM (tensor): split then mma; launch #4 is the GEMM (profiled)
    split_kernel<<<(N_NODES * IN_DIM / 4 + 255) / 256, 256>>>(x, -1, N_NODES * IN_DIM / 4, 0);        // 2
    split_kernel<<<(F_DIM * IN_DIM / 4 + 255) / 256, 256>>>(conv_W, -1, F_DIM * IN_DIM / 4, 1);       // 3
    gemm_tc_kernel<<<dim3(F_DIM / 128, N_NODES / 128), 256>>>(nullptr, BUF_H, F_DIM, IN_DIM, 0);      // 4

    // CSR build
    zero_deg_kernel<<<(N_NODES + 255) / 256, 256>>>();
    hist_kernel<<<(E_IN + 255) / 256, 256>>>(ei);
    scan_kernel<<<1, 1024>>>();
    scatter_kernel<<<(E_IN + 255) / 256, 256>>>(ei);

    attn_scores_kernel<<<(N_NODES * HEADS * 32 + 255) / 256, 256>>>(att_src, att_dst);
    gat_agg_kernel<<<N_NODES, 128>>>(conv_b);

    // MLP big layers on tensor cores
    split_kernel<<<(N_NODES * F_DIM / 4 + 255) / 256, 256>>>(nullptr, BUF_GAT, N_NODES * F_DIM / 4, 0);
    split_kernel<<<(256 * 512 / 4 + 255) / 256, 256>>>(Wa, -1, 256 * 512 / 4, 1);
    gemm_tc_kernel<<<dim3(256 / 128, N_NODES / 128), 256>>>(ba, BUF_H1, 256, 512, 1);

    split_kernel<<<(N_NODES * 256 / 4 + 255) / 256, 256>>>(nullptr, BUF_H1, N_NODES * 256 / 4, 0);
    split_kernel<<<(128 * 256 / 4 + 255) / 256, 256>>>(W1, -1, 128 * 256 / 4, 1);
    gemm_tc_kernel<<<dim3(128 / 128, N_NODES / 128), 256>>>(b1, BUF_H2, 128, 256, 1);

    // small layers stay fp32 SIMT
    gemm_kernel<<<dim3(1, N_NODES / 64), 256>>>(BUF_H2, W2, b2, BUF_H3, 64, 128, 1);
    gemm_kernel<<<dim3(1, N_NODES / 64), 256>>>(BUF_H3, W3, b3, BUF_H4, 32, 64, 1);
    final_layer_kernel<<<N_NODES / 256, 256>>>(W4, b4);

    cdist_kernel<<<dim3(N_NODES / 128, N_NODES / 128), 256>>>(out);
}